// round 9
// baseline (speedup 1.0000x reference)
#include <cuda_runtime.h>
#include <cuda_bf16.h>
#include <cuda_fp16.h>
#include <cstdint>

// ---------------------------------------------------------------------------
// Problem constants
// ---------------------------------------------------------------------------
#define D_MODEL 1024
#define BATCH   16
#define LQ      1024
#define NBE     256
#define ML (BATCH * LQ)    // 16384
#define MB (BATCH * NBE)   // 4096

// ---------------------------------------------------------------------------
// Scratch (__device__ globals; no allocation anywhere)
// ---------------------------------------------------------------------------
__device__ __half  g_qh  [ML * D_MODEL];                      // query fp16 (1 plane)
__device__ __half  g_WQTh[D_MODEL * D_MODEL], g_WQTl[D_MODEL * D_MODEL]; // WQ^T
__device__ __half  g_WKTh[D_MODEL * D_MODEL], g_WKTl[D_MODEL * D_MODEL]; // WK^T
__device__ __half  g_WOh [D_MODEL * D_MODEL], g_WOl [D_MODEL * D_MODEL]; // WO
__device__ __half  g_Gh  [MB * D_MODEL], g_Gl [MB * D_MODEL]; // gathered ents
__device__ __half  g_T12 [2048 * D_MODEL];                    // [T1; T2] fp16
__device__ __half  g_EQEO[MB * 2048];                         // [EQ | EO] fp16
__device__ __half  g_EOT [MB * D_MODEL];                      // EO^T per batch
__device__ float   g_sb  [MB];                                // bQ.ENT score bias
__device__ float   g_vb  [1025];                              // WK^T bQ, [1024]=bQ.bK
__device__ float   g_b2  [2048];                              // [bK@WQ | bK@WO^T]
__device__ float   g_S   [ML * NBE];                          // scores fp32
__device__ __half  g_Wh  [ML * NBE], g_Wl [ML * NBE];         // softmax wts fp16
__device__ float   g_P   [ML * D_MODEL];                      // pre-LN fp32

// ---------------------------------------------------------------------------
// Helpers
// ---------------------------------------------------------------------------
__device__ __forceinline__ void split1h(float x, __half& h, __half& l) {
    h = __float2half_rn(x);
    l = __float2half_rn(x - __half2float(h));
}

__device__ __forceinline__ void cp16(uint32_t dst, const void* src) {
    asm volatile("cp.async.cg.shared.global [%0], [%1], 16;"
                 :: "r"(dst), "l"(src) : "memory");
}
__device__ __forceinline__ void ldsm4(uint32_t* r, uint32_t addr) {
    asm volatile("ldmatrix.sync.aligned.m8n8.x4.shared.b16 {%0,%1,%2,%3}, [%4];"
                 : "=r"(r[0]), "=r"(r[1]), "=r"(r[2]), "=r"(r[3]) : "r"(addr));
}
__device__ __forceinline__ void mma_f16(float* c, const uint32_t* a,
                                        uint32_t b0, uint32_t b1) {
    asm volatile(
        "mma.sync.aligned.m16n8k16.row.col.f32.f16.f16.f32 "
        "{%0,%1,%2,%3}, {%4,%5,%6,%7}, {%8,%9}, {%0,%1,%2,%3};"
        : "+f"(c[0]), "+f"(c[1]), "+f"(c[2]), "+f"(c[3])
        : "r"(a[0]), "r"(a[1]), "r"(a[2]), "r"(a[3]), "r"(b0), "r"(b1));
}

#define BKC 32
#define SKB 80                        // smem row stride bytes (40 halves)
#define PLANE_B (128 * SKB)           // 10240 B per plane per stage

// ---------------------------------------------------------------------------
// gemm2: fp16 NT GEMM: C[bz][M,N] = (Ah (+Al)) @ B^T (+bias)
// A ATERMS fp16 planes (lda=K), B single fp16 plane (row stride ldb).
// Output fp16 (F16OUT) or fp32.  bias[bz*sBias + col].
// CTA 128x128, BK=32, 8 warps (2x4, warp tile 64x32),
// 2-stage cp.async pipeline, 256 threads, 2 CTAs/SM.
// ---------------------------------------------------------------------------
template<int ATERMS, bool F16OUT>
__global__ void __launch_bounds__(256, 2) gemm2(
    const __half* __restrict__ Ahp, const __half* __restrict__ Alp, long sA,
    const __half* __restrict__ Bp, long sB, int ldb,
    float* __restrict__ Cf, __half* __restrict__ Ch, long sC,
    int N, int K,
    const float* __restrict__ bias, long sBias)
{
    constexpr int PLANES  = ATERMS + 1;
    constexpr int STAGE_B = PLANES * PLANE_B;
    constexpr int BOFF    = ATERMS * PLANE_B;

    extern __shared__ char smc[];
    const uint32_t smb = (uint32_t)__cvta_generic_to_shared(smc);

    const int tid  = threadIdx.x;
    const int wid  = tid >> 5;
    const int lane = tid & 31;
    const int wm   = wid >> 2;
    const int wn   = wid & 3;
    const int gq   = lane >> 2;
    const int tg   = lane & 3;

    const int mtile = blockIdx.y * 128;
    const int ntile = blockIdx.x * 128;
    const int bz    = blockIdx.z;
    Ahp += (long)bz * sA;
    if (ATERMS == 2) Alp += (long)bz * sA;
    Bp  += (long)bz * sB;

    const int nch = K >> 5;

    float acc[4][4][4];
#pragma unroll
    for (int i = 0; i < 4; i++)
#pragma unroll
        for (int j = 0; j < 4; j++)
#pragma unroll
            for (int q = 0; q < 4; q++) acc[i][j][q] = 0.f;

    const int lrow = tid >> 2;
    const int lseg = tid & 3;
    const long aoff = (long)(mtile + lrow) * K + lseg * 8;
    const long boff = (long)(ntile + lrow) * ldb + lseg * 8;
    const long ahalf = (long)64 * K;
    const long bhalf = (long)64 * ldb;
    const uint32_t sdst = lrow * SKB + lseg * 16;
    const uint32_t shalf = 64 * SKB;

    auto load_chunk = [&](int c, int s) {
        const long kofs = (long)c * BKC;
        const uint32_t sb = smb + s * STAGE_B + sdst;
        cp16(sb,               Ahp + aoff + kofs);
        cp16(sb + shalf,       Ahp + aoff + ahalf + kofs);
        if (ATERMS == 2) {
            cp16(sb + PLANE_B,          Alp + aoff + kofs);
            cp16(sb + PLANE_B + shalf,  Alp + aoff + ahalf + kofs);
        }
        cp16(sb + BOFF,         Bp + boff + kofs);
        cp16(sb + BOFF + shalf, Bp + boff + bhalf + kofs);
    };

    load_chunk(0, 0);
    asm volatile("cp.async.commit_group;" ::: "memory");

    const int lr = (lane & 7) + ((lane >> 3) & 1) * 8;
    const int lc = ((lane >> 4) & 1) * 16;

    for (int c = 0; c < nch; c++) {
        const int s = c & 1;
        if (c + 1 < nch) {
            load_chunk(c + 1, s ^ 1);
            asm volatile("cp.async.commit_group;" ::: "memory");
            asm volatile("cp.async.wait_group 1;" ::: "memory");
        } else {
            asm volatile("cp.async.wait_group 0;" ::: "memory");
        }
        __syncthreads();
        const uint32_t stb = smb + s * STAGE_B;

#pragma unroll
        for (int kk = 0; kk < 2; kk++) {
            uint32_t bh[2][4];
#pragma unroll
            for (int h = 0; h < 2; h++) {
                uint32_t bd = stb + BOFF
                            + (uint32_t)(wn * 32 + h * 16 + lr) * SKB + kk * 32 + lc;
                ldsm4(bh[h], bd);
            }
#pragma unroll
            for (int mp = 0; mp < 2; mp++) {
                uint32_t ah[2][4], al[2][4];
#pragma unroll
                for (int m2 = 0; m2 < 2; m2++) {
                    uint32_t ad = stb
                        + (uint32_t)(wm * 64 + (mp * 2 + m2) * 16 + lr) * SKB
                        + kk * 32 + lc;
                    ldsm4(ah[m2], ad);
                    if (ATERMS == 2) ldsm4(al[m2], ad + PLANE_B);
                }
#pragma unroll
                for (int m2 = 0; m2 < 2; m2++)
#pragma unroll
                    for (int h = 0; h < 2; h++)
#pragma unroll
                        for (int j = 0; j < 2; j++) {
                            float* cc = acc[mp * 2 + m2][h * 2 + j];
                            mma_f16(cc, ah[m2], bh[h][j], bh[h][j + 2]);
                            if (ATERMS == 2)
                                mma_f16(cc, al[m2], bh[h][j], bh[h][j + 2]);
                        }
            }
        }
        __syncthreads();
    }

#pragma unroll
    for (int mt = 0; mt < 4; mt++) {
        const int r0 = mtile + wm * 64 + mt * 16 + gq;
#pragma unroll
        for (int nt = 0; nt < 4; nt++) {
            const int col = ntile + wn * 32 + nt * 8 + tg * 2;
            float bx = 0.f, by = 0.f;
            if (bias != nullptr) {
                float2 bb = *(const float2*)(bias + bz * sBias + col);
                bx = bb.x; by = bb.y;
            }
            float o00 = acc[mt][nt][0] + bx;
            float o01 = acc[mt][nt][1] + by;
            float o10 = acc[mt][nt][2] + bx;
            float o11 = acc[mt][nt][3] + by;
            const long i0 = (long)bz * sC + (long)r0 * N + col;
            const long i1 = i0 + (long)8 * N;
            if (F16OUT) {
                __half2 p0, p1;
                p0.x = __float2half_rn(o00); p0.y = __float2half_rn(o01);
                p1.x = __float2half_rn(o10); p1.y = __float2half_rn(o11);
                *(__half2*)(Ch + i0) = p0;
                *(__half2*)(Ch + i1) = p1;
            } else {
                *(float2*)(Cf + i0) = make_float2(o00, o01);
                *(float2*)(Cf + i1) = make_float2(o10, o11);
            }
        }
    }
}

#define GSMEM_A2 (2 * 3 * PLANE_B)    // 61440
#define GSMEM_A1 (2 * 2 * PLANE_B)    // 40960

// ---------------------------------------------------------------------------
// query fp32 -> single fp16 plane (RN)
// ---------------------------------------------------------------------------
__global__ void tohalf(const float* __restrict__ x, __half* __restrict__ h, int n4)
{
    int i = blockIdx.x * blockDim.x + threadIdx.x;
    if (i >= n4) return;
    float4 v = ((const float4*)x)[i];
    __half hh[4];
    hh[0] = __float2half_rn(v.x); hh[1] = __float2half_rn(v.y);
    hh[2] = __float2half_rn(v.z); hh[3] = __float2half_rn(v.w);
    ((uint2*)h)[i] = *(uint2*)hh;
}

// fp32 -> fp16 hi/lo split (WO)
__global__ void split_f16(const float* __restrict__ x,
                          __half* __restrict__ h, __half* __restrict__ l, int n4)
{
    int i = blockIdx.x * blockDim.x + threadIdx.x;
    if (i >= n4) return;
    float4 v = ((const float4*)x)[i];
    __half hh[4], ll[4];
    split1h(v.x, hh[0], ll[0]); split1h(v.y, hh[1], ll[1]);
    split1h(v.z, hh[2], ll[2]); split1h(v.w, hh[3], ll[3]);
    ((uint2*)h)[i] = *(uint2*)hh;
    ((uint2*)l)[i] = *(uint2*)ll;
}

// split + transpose (D,D) fp32 -> fp16 planes of W^T
__global__ void split_tr(const float* __restrict__ W,
                         __half* __restrict__ Th, __half* __restrict__ Tl)
{
    __shared__ float t[32][33];
    const int c0 = blockIdx.x * 32;
    const int r0 = blockIdx.y * 32;
    const int tx = threadIdx.x, ty = threadIdx.y;
#pragma unroll
    for (int i = 0; i < 32; i += 8)
        t[ty + i][tx] = W[(long)(r0 + ty + i) * D_MODEL + c0 + tx];
    __syncthreads();
#pragma unroll
    for (int i = 0; i < 32; i += 8) {
        float v = t[tx][ty + i];
        __half h, l;
        split1h(v, h, l);
        const long o = (long)(c0 + ty + i) * D_MODEL + r0 + tx;
        Th[o] = h;  Tl[o] = l;
    }
}

// ---------------------------------------------------------------------------
// prep_vec: b2[0:1024]=bK@WQ, b2[1024:2048]=bK@WO^T, vb[0:1024]=WK^T bQ,
// vb[1024]=bQ.bK.  One block per output element.
// ---------------------------------------------------------------------------
__global__ void prep_vec(const __half* __restrict__ WQTh,
                         const __half* __restrict__ WQTl,
                         const float* __restrict__ WO,
                         const __half* __restrict__ WKTh,
                         const __half* __restrict__ WKTl,
                         const float* __restrict__ bK,
                         const float* __restrict__ bQ,
                         float* __restrict__ b2, float* __restrict__ vb)
{
    const int n = blockIdx.x;
    const int t = threadIdx.x;
    float s = 0.f;

    if (n < 1024) {
        const uint2 h2 = ((const uint2*)(WQTh + (long)n * D_MODEL))[t];
        const uint2 l2 = ((const uint2*)(WQTl + (long)n * D_MODEL))[t];
        const __half* hp = (const __half*)&h2;
        const __half* lp = (const __half*)&l2;
        float4 b = ((const float4*)bK)[t];
        s = (__half2float(hp[0]) + __half2float(lp[0])) * b.x
          + (__half2float(hp[1]) + __half2float(lp[1])) * b.y
          + (__half2float(hp[2]) + __half2float(lp[2])) * b.z
          + (__half2float(hp[3]) + __half2float(lp[3])) * b.w;
    } else if (n < 2048) {
        float4 w = ((const float4*)(WO + (long)(n - 1024) * D_MODEL))[t];
        float4 b = ((const float4*)bK)[t];
        s = w.x * b.x + w.y * b.y + w.z * b.z + w.w * b.w;
    } else if (n < 3072) {
        const uint2 h2 = ((const uint2*)(WKTh + (long)(n - 2048) * D_MODEL))[t];
        const uint2 l2 = ((const uint2*)(WKTl + (long)(n - 2048) * D_MODEL))[t];
        const __half* hp = (const __half*)&h2;
        const __half* lp = (const __half*)&l2;
        float4 b = ((const float4*)bQ)[t];
        s = (__half2float(hp[0]) + __half2float(lp[0])) * b.x
          + (__half2float(hp[1]) + __half2float(lp[1])) * b.y
          + (__half2float(hp[2]) + __half2float(lp[2])) * b.z
          + (__half2float(hp[3]) + __half2float(lp[3])) * b.w;
    } else {
        float4 q = ((const float4*)bQ)[t];
        float4 b = ((const float4*)bK)[t];
        s = q.x * b.x + q.y * b.y + q.z * b.z + q.w * b.w;
    }

    __shared__ float red[8];
#pragma unroll
    for (int o = 16; o; o >>= 1) s += __shfl_xor_sync(0xffffffffu, s, o);
    if ((t & 31) == 0) red[t >> 5] = s;
    __syncthreads();
    if (t == 0) {
        float tot = 0.f;
#pragma unroll
        for (int i = 0; i < 8; i++) tot += red[i];
        if (n < 2048)      b2[n] = tot;
        else if (n < 3072) vb[n - 2048] = tot;
        else               vb[1024] = tot;
    }
}

// ---------------------------------------------------------------------------
// gather + fp16 split + score-bias: G[r]=split(E[max(idx,0)]), sb[r]=G_r.v + c0
// ---------------------------------------------------------------------------
__global__ void gather_sb(const float* __restrict__ E,
                          const int* __restrict__ idx,
                          const float* __restrict__ vb,
                          __half* __restrict__ Gh, __half* __restrict__ Gl,
                          float* __restrict__ sb)
{
    const int r = blockIdx.x;
    int s = idx[r];
    if (s < 0) s = 0;
    const int i = threadIdx.x;
    float4 v = ((const float4*)(E + (long)s * D_MODEL))[i];
    __half hh[4], ll[4];
    split1h(v.x, hh[0], ll[0]); split1h(v.y, hh[1], ll[1]);
    split1h(v.z, hh[2], ll[2]); split1h(v.w, hh[3], ll[3]);
    ((uint2*)(Gh + (long)r * D_MODEL))[i] = *(uint2*)hh;
    ((uint2*)(Gl + (long)r * D_MODEL))[i] = *(uint2*)ll;

    float4 w = ((const float4*)vb)[i];
    float d = v.x * w.x + v.y * w.y + v.z * w.z + v.w * w.w;
    __shared__ float red[8];
#pragma unroll
    for (int o = 16; o; o >>= 1) d += __shfl_xor_sync(0xffffffffu, d, o);
    if ((i & 31) == 0) red[i >> 5] = d;
    __syncthreads();
    if (i == 0) {
        float tot = vb[1024];
#pragma unroll
        for (int k = 0; k < 8; k++) tot += red[k];
        sb[r] = tot;
    }
}

// ---------------------------------------------------------------------------
// per-batch fp16 transpose of the EO half of EQEO -> EOT[b] (D x NBE)
// ---------------------------------------------------------------------------
__global__ void transpose_f16(const __half* __restrict__ EQEO,
                              __half* __restrict__ EOT)
{
    __shared__ __half t[32][34];
    const int b  = blockIdx.z;
    const int c0 = blockIdx.x * 32;
    const int r0 = blockIdx.y * 32;
    const int tx = threadIdx.x, ty = threadIdx.y;
#pragma unroll
    for (int i = 0; i < 32; i += 8)
        t[ty + i][tx] = EQEO[(long)(b * NBE + r0 + ty + i) * 2048 + 1024 + c0 + tx];
    __syncthreads();
#pragma unroll
    for (int i = 0; i < 32; i += 8)
        EOT[(long)b * NBE * D_MODEL + (long)(c0 + ty + i) * NBE + r0 + tx]
            = t[tx][ty + i];
}

// ---------------------------------------------------------------------------
// masked softmax over NB=256 + d^-0.5 scale -> fp16 hi/lo planes
// ---------------------------------------------------------------------------
__global__ void softmax_split(const float* __restrict__ S,
                              const int* __restrict__ idx,
                              __half* __restrict__ Wh, __half* __restrict__ Wl)
{
    const int row = blockIdx.x;
    const int b   = row >> 10;
    const int n   = threadIdx.x;
    const long off = (long)row * NBE + n;

    float s = S[off];
    if (idx[b * NBE + n] < 0) s = -100000.0f;

    __shared__ float red[8];
    float m = s;
#pragma unroll
    for (int o = 16; o; o >>= 1) m = fmaxf(m, __shfl_xor_sync(0xffffffffu, m, o));
    if ((n & 31) == 0) red[n >> 5] = m;
    __syncthreads();
    float mall = red[0];
#pragma unroll
    for (int i = 1; i < 8; i++) mall = fmaxf(mall, red[i]);

    float e = expf(s - mall);
    __syncthreads();
    float t = e;
#pragma unroll
    for (int o = 16; o; o >>= 1) t += __shfl_xor_sync(0xffffffffu, t, o);
    if ((n & 31) == 0) red[n >> 5] = t;
    __syncthreads();
    float sum = 0.f;
#pragma unroll
    for (int i = 0; i < 8; i++) sum += red[i];

    float w = e * (0.03125f / sum);
    __half h, l;
    split1h(w, h, l);
    Wh[off] = h;
    Wl[off] = l;
}

// ---------------------------------------------------------------------------
// Row LayerNorm over D=1024 (biased var, eps=1e-5).
// ---------------------------------------------------------------------------
__global__ void layernorm_k(const float* __restrict__ X,
                            const float* __restrict__ g,
                            const float* __restrict__ b,
                            float* __restrict__ O)
{
    const int row = blockIdx.x;
    const int t   = threadIdx.x;
    const float* x = X + (long)row * D_MODEL;

    float4 v = *(const float4*)(x + t * 4);
    float s  = v.x + v.y + v.z + v.w;
    float sq = v.x * v.x + v.y * v.y + v.z * v.z + v.w * v.w;

    __shared__ float rs[8], rq[8];
#pragma unroll
    for (int o = 16; o; o >>= 1) {
        s  += __shfl_xor_sync(0xffffffffu, s,  o);
        sq += __shfl_xor_sync(0xffffffffu, sq, o);
    }
    if ((t & 31) == 0) { rs[t >> 5] = s; rq[t >> 5] = sq; }
    __syncthreads();
    float S = 0.f, Q = 0.f;
#pragma unroll
    for (int i = 0; i < 8; i++) { S += rs[i]; Q += rq[i]; }

    float mu  = S * (1.f / 1024.f);
    float var = Q * (1.f / 1024.f) - mu * mu;
    float inv = rsqrtf(var + 1e-5f);

    float4 gg = *(const float4*)(g + t * 4);
    float4 bb = *(const float4*)(b + t * 4);
    float4 o;
    o.x = (v.x - mu) * inv * gg.x + bb.x;
    o.y = (v.y - mu) * inv * gg.y + bb.y;
    o.z = (v.z - mu) * inv * gg.z + bb.z;
    o.w = (v.w - mu) * inv * gg.w + bb.w;
    *(float4*)(O + (long)row * D_MODEL + t * 4) = o;
}

// ---------------------------------------------------------------------------
extern "C" void kernel_launch(void* const* d_in, const int* in_sizes, int n_in,
                              void* d_out, int out_size)
{
    const float* query   = (const float*)d_in[0];
    const float* ent_emb = (const float*)d_in[1];
    const int*   idx     = (const int*)  d_in[2];
    const float* WQ_w = (const float*)d_in[4];
    const float* WQ_b = (const float*)d_in[5];
    const float* WK_w = (const float*)d_in[6];
    const float* WK_b = (const float*)d_in[7];
    const float* WO_w = (const float*)d_in[8];
    const float* WO_b = (const float*)d_in[9];
    const float* ln_g = (const float*)d_in[10];
    const float* ln_b = (const float*)d_in[11];
    float* out = (float*)d_out;

    __half *qh, *Gh, *Gl, *T12, *EQEO, *EOT, *Wh, *Wl;
    __half *WQTh, *WQTl, *WKTh, *WKTl, *WOh, *WOl;
    float *sb, *vb, *b2, *S, *P;
    cudaGetSymbolAddress((void**)&qh,   g_qh);
    cudaGetSymbolAddress((void**)&WQTh, g_WQTh); cudaGetSymbolAddress((void**)&WQTl, g_WQTl);
    cudaGetSymbolAddress((void**)&WKTh, g_WKTh); cudaGetSymbolAddress((void**)&WKTl, g_WKTl);
    cudaGetSymbolAddress((void**)&WOh,  g_WOh);  cudaGetSymbolAddress((void**)&WOl,  g_WOl);
    cudaGetSymbolAddress((void**)&Gh,   g_Gh);   cudaGetSymbolAddress((void**)&Gl,   g_Gl);
    cudaGetSymbolAddress((void**)&T12,  g_T12);
    cudaGetSymbolAddress((void**)&EQEO, g_EQEO);
    cudaGetSymbolAddress((void**)&EOT,  g_EOT);
    cudaGetSymbolAddress((void**)&Wh,   g_Wh);   cudaGetSymbolAddress((void**)&Wl,   g_Wl);
    cudaGetSymbolAddress((void**)&sb,   g_sb);
    cudaGetSymbolAddress((void**)&vb,   g_vb);
    cudaGetSymbolAddress((void**)&b2,   g_b2);
    cudaGetSymbolAddress((void**)&S,    g_S);
    cudaGetSymbolAddress((void**)&P,    g_P);

    cudaFuncSetAttribute((const void*)gemm2<2, true >,
        cudaFuncAttributeMaxDynamicSharedMemorySize, GSMEM_A2);
    cudaFuncSetAttribute((const void*)gemm2<2, false>,
        cudaFuncAttributeMaxDynamicSharedMemorySize, GSMEM_A2);
    cudaFuncSetAttribute((const void*)gemm2<1, false>,
        cudaFuncAttributeMaxDynamicSharedMemorySize, GSMEM_A1);

    const int DD4 = D_MODEL * D_MODEL / 4;

    // 0. input preprocessing
    tohalf<<<(ML * D_MODEL / 4 + 255) / 256, 256>>>(query, qh, ML * D_MODEL / 4);
    split_f16<<<(DD4 + 255) / 256, 256>>>(WO_w, WOh, WOl, DD4);
    split_tr<<<dim3(32, 32), dim3(32, 8)>>>(WQ_w, WQTh, WQTl);
    split_tr<<<dim3(32, 32), dim3(32, 8)>>>(WK_w, WKTh, WKTl);
    prep_vec<<<3073, 256>>>(WQTh, WQTl, WO_w, WKTh, WKTl, WK_b, WQ_b, b2, vb);
    gather_sb<<<MB, 256>>>(ent_emb, idx, vb, Gh, Gl, sb);

    // 1. weight products (2-term fp16): T1 = WQ^T@WK, T2 = WO@WK, fp16 out
    gemm2<2, true><<<dim3(8, 8, 1), 256, GSMEM_A2>>>(
        WQTh, WQTl, 0, WKTh, 0, D_MODEL, nullptr, T12, 0,
        D_MODEL, D_MODEL, nullptr, 0);
    gemm2<2, true><<<dim3(8, 8, 1), 256, GSMEM_A2>>>(
        WOh, WOl, 0, WKTh, 0, D_MODEL, nullptr, T12 + (long)1024 * D_MODEL, 0,
        D_MODEL, D_MODEL, nullptr, 0);

    // 2. EQEO = G @ [T1;T2]^T + bias2   [4096 x 2048 x 1024], fp16 out
    gemm2<2, true><<<dim3(16, 32, 1), 256, GSMEM_A2>>>(
        Gh, Gl, 0, T12, 0, D_MODEL, nullptr, EQEO, 0,
        2048, D_MODEL, b2, 0);

    // 3. S[b] = query[b] @ EQ[b]^T + sb[b]   (1-term A)
    gemm2<1, false><<<dim3(2, 8, BATCH), 256, GSMEM_A1>>>(
        qh, nullptr, (long)LQ * D_MODEL, EQEO, (long)NBE * 2048, 2048,
        S, nullptr, (long)LQ * NBE, NBE, D_MODEL, sb, NBE);

    // 4. masked softmax + d^-0.5 -> fp16 planes
    softmax_split<<<ML, NBE>>>(S, idx, Wh, Wl);

    // 5. EOT[b] = EO[b]^T
    transpose_f16<<<dim3(32, 8, BATCH), dim3(32, 8)>>>(EQEO, EOT);

    // 6. P[b] = W[b] @ EOT[b]^T + bO   [16 x (1024 x 1024 x 256)]
    gemm2<2, false><<<dim3(8, 8, BATCH), 256, GSMEM_A2>>>(
        Wh, Wl, (long)LQ * NBE, EOT, (long)D_MODEL * NBE, NBE,
        P, nullptr, (long)LQ * D_MODEL, D_MODEL, NBE, WO_b, 0);

    // 7. LayerNorm -> out
    layernorm_k<<<ML, 256>>>(P, ln_g, ln_b, out);
}

// round 10
// speedup vs baseline: 1.7381x; 1.7381x over previous
#include <cuda_runtime.h>
#include <cuda_bf16.h>
#include <cuda_fp16.h>
#include <cstdint>

// ---------------------------------------------------------------------------
// Problem constants
// ---------------------------------------------------------------------------
#define D_MODEL 1024
#define BATCH   16
#define LQ      1024
#define NBE     256
#define ML (BATCH * LQ)    // 16384
#define MB (BATCH * NBE)   // 4096

// ---------------------------------------------------------------------------
// Scratch (__device__ globals; no allocation anywhere)
// ---------------------------------------------------------------------------
__device__ __half  g_qh  [ML * D_MODEL];                      // query fp16 (1 plane)
__device__ __half  g_WQTh[D_MODEL * D_MODEL], g_WQTl[D_MODEL * D_MODEL]; // WQ^T
__device__ __half  g_WKTh[D_MODEL * D_MODEL], g_WKTl[D_MODEL * D_MODEL]; // WK^T
__device__ __half  g_WOh [D_MODEL * D_MODEL], g_WOl [D_MODEL * D_MODEL]; // WO
__device__ __half  g_Gh  [MB * D_MODEL];                      // gathered ents (1 plane)
__device__ __half  g_T12 [2048 * D_MODEL];                    // [T1; T2] fp16
__device__ __half  g_EQEO[MB * 2048];                         // [EQ | EO] fp16
__device__ __half  g_EOT [MB * D_MODEL];                      // EO^T per batch
__device__ float   g_sb  [MB];                                // bQ.ENT score bias
__device__ float   g_vb  [1025];                              // WK^T bQ, [1024]=bQ.bK
__device__ float   g_b2  [2048];                              // [bK@WQ | bK@WO^T]
__device__ float   g_S   [ML * NBE];                          // scores fp32
__device__ __half  g_Wh  [ML * NBE], g_Wl [ML * NBE];         // softmax wts fp16
__device__ float   g_P   [ML * D_MODEL];                      // pre-LN fp32

// ---------------------------------------------------------------------------
// Helpers
// ---------------------------------------------------------------------------
__device__ __forceinline__ void split1h(float x, __half& h, __half& l) {
    h = __float2half_rn(x);
    l = __float2half_rn(x - __half2float(h));
}

__device__ __forceinline__ void cp16(uint32_t dst, const void* src) {
    asm volatile("cp.async.cg.shared.global [%0], [%1], 16;"
                 :: "r"(dst), "l"(src) : "memory");
}
__device__ __forceinline__ void ldsm4(uint32_t* r, uint32_t addr) {
    asm volatile("ldmatrix.sync.aligned.m8n8.x4.shared.b16 {%0,%1,%2,%3}, [%4];"
                 : "=r"(r[0]), "=r"(r[1]), "=r"(r[2]), "=r"(r[3]) : "r"(addr));
}
__device__ __forceinline__ void mma_f16(float* c, const uint32_t* a,
                                        uint32_t b0, uint32_t b1) {
    asm volatile(
        "mma.sync.aligned.m16n8k16.row.col.f32.f16.f16.f32 "
        "{%0,%1,%2,%3}, {%4,%5,%6,%7}, {%8,%9}, {%0,%1,%2,%3};"
        : "+f"(c[0]), "+f"(c[1]), "+f"(c[2]), "+f"(c[3])
        : "r"(a[0]), "r"(a[1]), "r"(a[2]), "r"(a[3]), "r"(b0), "r"(b1));
}

#define BKC 32
#define SKB 80                        // smem row stride bytes (40 halves)
#define PLANE_B (128 * SKB)           // 10240 B per plane per stage

// ---------------------------------------------------------------------------
// gemm2: fp16 NT GEMM: C[bz][M,N] = (Ah (+Al)) @ B^T (+bias)
// A ATERMS fp16 planes (lda=K), B single fp16 plane (row stride ldb).
// Output fp16 (F16OUT) or fp32.  bias[bz*sBias + col].
// CTA 128x128, BK=32, 8 warps (2x4, warp tile 64x32),
// 2-stage cp.async pipeline, 256 threads, 2 CTAs/SM.
// ---------------------------------------------------------------------------
template<int ATERMS, bool F16OUT>
__global__ void __launch_bounds__(256, 2) gemm2(
    const __half* __restrict__ Ahp, const __half* __restrict__ Alp, long sA,
    const __half* __restrict__ Bp, long sB, int ldb,
    float* __restrict__ Cf, __half* __restrict__ Ch, long sC,
    int N, int K,
    const float* __restrict__ bias, long sBias)
{
    constexpr int PLANES  = ATERMS + 1;
    constexpr int STAGE_B = PLANES * PLANE_B;
    constexpr int BOFF    = ATERMS * PLANE_B;

    extern __shared__ char smc[];
    const uint32_t smb = (uint32_t)__cvta_generic_to_shared(smc);

    const int tid  = threadIdx.x;
    const int wid  = tid >> 5;
    const int lane = tid & 31;
    const int wm   = wid >> 2;
    const int wn   = wid & 3;
    const int gq   = lane >> 2;
    const int tg   = lane & 3;

    const int mtile = blockIdx.y * 128;
    const int ntile = blockIdx.x * 128;
    const int bz    = blockIdx.z;
    Ahp += (long)bz * sA;
    if (ATERMS == 2) Alp += (long)bz * sA;
    Bp  += (long)bz * sB;

    const int nch = K >> 5;

    float acc[4][4][4];
#pragma unroll
    for (int i = 0; i < 4; i++)
#pragma unroll
        for (int j = 0; j < 4; j++)
#pragma unroll
            for (int q = 0; q < 4; q++) acc[i][j][q] = 0.f;

    const int lrow = tid >> 2;
    const int lseg = tid & 3;
    const long aoff = (long)(mtile + lrow) * K + lseg * 8;
    const long boff = (long)(ntile + lrow) * ldb + lseg * 8;
    const long ahalf = (long)64 * K;
    const long bhalf = (long)64 * ldb;
    const uint32_t sdst = lrow * SKB + lseg * 16;
    const uint32_t shalf = 64 * SKB;

    auto load_chunk = [&](int c, int s) {
        const long kofs = (long)c * BKC;
        const uint32_t sb = smb + s * STAGE_B + sdst;
        cp16(sb,               Ahp + aoff + kofs);
        cp16(sb + shalf,       Ahp + aoff + ahalf + kofs);
        if (ATERMS == 2) {
            cp16(sb + PLANE_B,          Alp + aoff + kofs);
            cp16(sb + PLANE_B + shalf,  Alp + aoff + ahalf + kofs);
        }
        cp16(sb + BOFF,         Bp + boff + kofs);
        cp16(sb + BOFF + shalf, Bp + boff + bhalf + kofs);
    };

    load_chunk(0, 0);
    asm volatile("cp.async.commit_group;" ::: "memory");

    const int lr = (lane & 7) + ((lane >> 3) & 1) * 8;
    const int lc = ((lane >> 4) & 1) * 16;

    for (int c = 0; c < nch; c++) {
        const int s = c & 1;
        if (c + 1 < nch) {
            load_chunk(c + 1, s ^ 1);
            asm volatile("cp.async.commit_group;" ::: "memory");
            asm volatile("cp.async.wait_group 1;" ::: "memory");
        } else {
            asm volatile("cp.async.wait_group 0;" ::: "memory");
        }
        __syncthreads();
        const uint32_t stb = smb + s * STAGE_B;

#pragma unroll
        for (int kk = 0; kk < 2; kk++) {
            uint32_t bh[2][4];
#pragma unroll
            for (int h = 0; h < 2; h++) {
                uint32_t bd = stb + BOFF
                            + (uint32_t)(wn * 32 + h * 16 + lr) * SKB + kk * 32 + lc;
                ldsm4(bh[h], bd);
            }
#pragma unroll
            for (int mp = 0; mp < 2; mp++) {
                uint32_t ah[2][4], al[2][4];
#pragma unroll
                for (int m2 = 0; m2 < 2; m2++) {
                    uint32_t ad = stb
                        + (uint32_t)(wm * 64 + (mp * 2 + m2) * 16 + lr) * SKB
                        + kk * 32 + lc;
                    ldsm4(ah[m2], ad);
                    if (ATERMS == 2) ldsm4(al[m2], ad + PLANE_B);
                }
#pragma unroll
                for (int m2 = 0; m2 < 2; m2++)
#pragma unroll
                    for (int h = 0; h < 2; h++)
#pragma unroll
                        for (int j = 0; j < 2; j++) {
                            float* cc = acc[mp * 2 + m2][h * 2 + j];
                            mma_f16(cc, ah[m2], bh[h][j], bh[h][j + 2]);
                            if (ATERMS == 2)
                                mma_f16(cc, al[m2], bh[h][j], bh[h][j + 2]);
                        }
            }
        }
        __syncthreads();
    }

#pragma unroll
    for (int mt = 0; mt < 4; mt++) {
        const int r0 = mtile + wm * 64 + mt * 16 + gq;
#pragma unroll
        for (int nt = 0; nt < 4; nt++) {
            const int col = ntile + wn * 32 + nt * 8 + tg * 2;
            float bx = 0.f, by = 0.f;
            if (bias != nullptr) {
                float2 bb = *(const float2*)(bias + bz * sBias + col);
                bx = bb.x; by = bb.y;
            }
            float o00 = acc[mt][nt][0] + bx;
            float o01 = acc[mt][nt][1] + by;
            float o10 = acc[mt][nt][2] + bx;
            float o11 = acc[mt][nt][3] + by;
            const long i0 = (long)bz * sC + (long)r0 * N + col;
            const long i1 = i0 + (long)8 * N;
            if (F16OUT) {
                __half2 p0, p1;
                p0.x = __float2half_rn(o00); p0.y = __float2half_rn(o01);
                p1.x = __float2half_rn(o10); p1.y = __float2half_rn(o11);
                *(__half2*)(Ch + i0) = p0;
                *(__half2*)(Ch + i1) = p1;
            } else {
                *(float2*)(Cf + i0) = make_float2(o00, o01);
                *(float2*)(Cf + i1) = make_float2(o10, o11);
            }
        }
    }
}

#define GSMEM_A2 (2 * 3 * PLANE_B)    // 61440
#define GSMEM_A1 (2 * 2 * PLANE_B)    // 40960

// ---------------------------------------------------------------------------
// query fp32 -> single fp16 plane (RN)
// ---------------------------------------------------------------------------
__global__ void tohalf(const float* __restrict__ x, __half* __restrict__ h, int n4)
{
    int i = blockIdx.x * blockDim.x + threadIdx.x;
    if (i >= n4) return;
    float4 v = ((const float4*)x)[i];
    __half hh[4];
    hh[0] = __float2half_rn(v.x); hh[1] = __float2half_rn(v.y);
    hh[2] = __float2half_rn(v.z); hh[3] = __float2half_rn(v.w);
    ((uint2*)h)[i] = *(uint2*)hh;
}

// fp32 -> fp16 hi/lo split (WO)
__global__ void split_f16(const float* __restrict__ x,
                          __half* __restrict__ h, __half* __restrict__ l, int n4)
{
    int i = blockIdx.x * blockDim.x + threadIdx.x;
    if (i >= n4) return;
    float4 v = ((const float4*)x)[i];
    __half hh[4], ll[4];
    split1h(v.x, hh[0], ll[0]); split1h(v.y, hh[1], ll[1]);
    split1h(v.z, hh[2], ll[2]); split1h(v.w, hh[3], ll[3]);
    ((uint2*)h)[i] = *(uint2*)hh;
    ((uint2*)l)[i] = *(uint2*)ll;
}

// split + transpose (D,D) fp32 -> fp16 planes of W^T  (CLOCK CANARY kernel)
__global__ void split_tr(const float* __restrict__ W,
                         __half* __restrict__ Th, __half* __restrict__ Tl)
{
    __shared__ float t[32][33];
    const int c0 = blockIdx.x * 32;
    const int r0 = blockIdx.y * 32;
    const int tx = threadIdx.x, ty = threadIdx.y;
#pragma unroll
    for (int i = 0; i < 32; i += 8)
        t[ty + i][tx] = W[(long)(r0 + ty + i) * D_MODEL + c0 + tx];
    __syncthreads();
#pragma unroll
    for (int i = 0; i < 32; i += 8) {
        float v = t[tx][ty + i];
        __half h, l;
        split1h(v, h, l);
        const long o = (long)(c0 + ty + i) * D_MODEL + r0 + tx;
        Th[o] = h;  Tl[o] = l;
    }
}

// ---------------------------------------------------------------------------
// prep_vec: b2[0:1024]=bK@WQ, b2[1024:2048]=bK@WO^T, vb[0:1024]=WK^T bQ,
// vb[1024]=bQ.bK.  One block per output element.
// ---------------------------------------------------------------------------
__global__ void prep_vec(const __half* __restrict__ WQTh,
                         const __half* __restrict__ WQTl,
                         const float* __restrict__ WO,
                         const __half* __restrict__ WKTh,
                         const __half* __restrict__ WKTl,
                         const float* __restrict__ bK,
                         const float* __restrict__ bQ,
                         float* __restrict__ b2, float* __restrict__ vb)
{
    const int n = blockIdx.x;
    const int t = threadIdx.x;
    float s = 0.f;

    if (n < 1024) {
        const uint2 h2 = ((const uint2*)(WQTh + (long)n * D_MODEL))[t];
        const uint2 l2 = ((const uint2*)(WQTl + (long)n * D_MODEL))[t];
        const __half* hp = (const __half*)&h2;
        const __half* lp = (const __half*)&l2;
        float4 b = ((const float4*)bK)[t];
        s = (__half2float(hp[0]) + __half2float(lp[0])) * b.x
          + (__half2float(hp[1]) + __half2float(lp[1])) * b.y
          + (__half2float(hp[2]) + __half2float(lp[2])) * b.z
          + (__half2float(hp[3]) + __half2float(lp[3])) * b.w;
    } else if (n < 2048) {
        float4 w = ((const float4*)(WO + (long)(n - 1024) * D_MODEL))[t];
        float4 b = ((const float4*)bK)[t];
        s = w.x * b.x + w.y * b.y + w.z * b.z + w.w * b.w;
    } else if (n < 3072) {
        const uint2 h2 = ((const uint2*)(WKTh + (long)(n - 2048) * D_MODEL))[t];
        const uint2 l2 = ((const uint2*)(WKTl + (long)(n - 2048) * D_MODEL))[t];
        const __half* hp = (const __half*)&h2;
        const __half* lp = (const __half*)&l2;
        float4 b = ((const float4*)bQ)[t];
        s = (__half2float(hp[0]) + __half2float(lp[0])) * b.x
          + (__half2float(hp[1]) + __half2float(lp[1])) * b.y
          + (__half2float(hp[2]) + __half2float(lp[2])) * b.z
          + (__half2float(hp[3]) + __half2float(lp[3])) * b.w;
    } else {
        float4 q = ((const float4*)bQ)[t];
        float4 b = ((const float4*)bK)[t];
        s = q.x * b.x + q.y * b.y + q.z * b.z + q.w * b.w;
    }

    __shared__ float red[8];
#pragma unroll
    for (int o = 16; o; o >>= 1) s += __shfl_xor_sync(0xffffffffu, s, o);
    if ((t & 31) == 0) red[t >> 5] = s;
    __syncthreads();
    if (t == 0) {
        float tot = 0.f;
#pragma unroll
        for (int i = 0; i < 8; i++) tot += red[i];
        if (n < 2048)      b2[n] = tot;
        else if (n < 3072) vb[n - 2048] = tot;
        else               vb[1024] = tot;
    }
}

// ---------------------------------------------------------------------------
// gather (single fp16 plane) + score-bias: G[r]=rn(E[max(idx,0)]),
// sb[r] = E_r . v + bQ.bK
// ---------------------------------------------------------------------------
__global__ void gather_sb(const float* __restrict__ E,
                          const int* __restrict__ idx,
                          const float* __restrict__ vb,
                          __half* __restrict__ Gh,
                          float* __restrict__ sb)
{
    const int r = blockIdx.x;
    int s = idx[r];
    if (s < 0) s = 0;
    const int i = threadIdx.x;
    float4 v = ((const float4*)(E + (long)s * D_MODEL))[i];
    __half hh[4];
    hh[0] = __float2half_rn(v.x); hh[1] = __float2half_rn(v.y);
    hh[2] = __float2half_rn(v.z); hh[3] = __float2half_rn(v.w);
    ((uint2*)(Gh + (long)r * D_MODEL))[i] = *(uint2*)hh;

    float4 w = ((const float4*)vb)[i];
    float d = v.x * w.x + v.y * w.y + v.z * w.z + v.w * w.w;
    __shared__ float red[8];
#pragma unroll
    for (int o = 16; o; o >>= 1) d += __shfl_xor_sync(0xffffffffu, d, o);
    if ((i & 31) == 0) red[i >> 5] = d;
    __syncthreads();
    if (i == 0) {
        float tot = vb[1024];
#pragma unroll
        for (int k = 0; k < 8; k++) tot += red[k];
        sb[r] = tot;
    }
}

// ---------------------------------------------------------------------------
// per-batch fp16 transpose of the EO half of EQEO -> EOT[b] (D x NBE)
// ---------------------------------------------------------------------------
__global__ void transpose_f16(const __half* __restrict__ EQEO,
                              __half* __restrict__ EOT)
{
    __shared__ __half t[32][34];
    const int b  = blockIdx.z;
    const int c0 = blockIdx.x * 32;
    const int r0 = blockIdx.y * 32;
    const int tx = threadIdx.x, ty = threadIdx.y;
#pragma unroll
    for (int i = 0; i < 32; i += 8)
        t[ty + i][tx] = EQEO[(long)(b * NBE + r0 + ty + i) * 2048 + 1024 + c0 + tx];
    __syncthreads();
#pragma unroll
    for (int i = 0; i < 32; i += 8)
        EOT[(long)b * NBE * D_MODEL + (long)(c0 + ty + i) * NBE + r0 + tx]
            = t[tx][ty + i];
}

// ---------------------------------------------------------------------------
// masked softmax over NB=256 + d^-0.5 scale -> fp16 hi/lo planes
// ---------------------------------------------------------------------------
__global__ void softmax_split(const float* __restrict__ S,
                              const int* __restrict__ idx,
                              __half* __restrict__ Wh, __half* __restrict__ Wl)
{
    const int row = blockIdx.x;
    const int b   = row >> 10;
    const int n   = threadIdx.x;
    const long off = (long)row * NBE + n;

    float s = S[off];
    if (idx[b * NBE + n] < 0) s = -100000.0f;

    __shared__ float red[8];
    float m = s;
#pragma unroll
    for (int o = 16; o; o >>= 1) m = fmaxf(m, __shfl_xor_sync(0xffffffffu, m, o));
    if ((n & 31) == 0) red[n >> 5] = m;
    __syncthreads();
    float mall = red[0];
#pragma unroll
    for (int i = 1; i < 8; i++) mall = fmaxf(mall, red[i]);

    float e = expf(s - mall);
    __syncthreads();
    float t = e;
#pragma unroll
    for (int o = 16; o; o >>= 1) t += __shfl_xor_sync(0xffffffffu, t, o);
    if ((n & 31) == 0) red[n >> 5] = t;
    __syncthreads();
    float sum = 0.f;
#pragma unroll
    for (int i = 0; i < 8; i++) sum += red[i];

    float w = e * (0.03125f / sum);
    __half h, l;
    split1h(w, h, l);
    Wh[off] = h;
    Wl[off] = l;
}

// ---------------------------------------------------------------------------
// Row LayerNorm over D=1024 (biased var, eps=1e-5).
// ---------------------------------------------------------------------------
__global__ void layernorm_k(const float* __restrict__ X,
                            const float* __restrict__ g,
                            const float* __restrict__ b,
                            float* __restrict__ O)
{
    const int row = blockIdx.x;
    const int t   = threadIdx.x;
    const float* x = X + (long)row * D_MODEL;

    float4 v = *(const float4*)(x + t * 4);
    float s  = v.x + v.y + v.z + v.w;
    float sq = v.x * v.x + v.y * v.y + v.z * v.z + v.w * v.w;

    __shared__ float rs[8], rq[8];
#pragma unroll
    for (int o = 16; o; o >>= 1) {
        s  += __shfl_xor_sync(0xffffffffu, s,  o);
        sq += __shfl_xor_sync(0xffffffffu, sq, o);
    }
    if ((t & 31) == 0) { rs[t >> 5] = s; rq[t >> 5] = sq; }
    __syncthreads();
    float S = 0.f, Q = 0.f;
#pragma unroll
    for (int i = 0; i < 8; i++) { S += rs[i]; Q += rq[i]; }

    float mu  = S * (1.f / 1024.f);
    float var = Q * (1.f / 1024.f) - mu * mu;
    float inv = rsqrtf(var + 1e-5f);

    float4 gg = *(const float4*)(g + t * 4);
    float4 bb = *(const float4*)(b + t * 4);
    float4 o;
    o.x = (v.x - mu) * inv * gg.x + bb.x;
    o.y = (v.y - mu) * inv * gg.y + bb.y;
    o.z = (v.z - mu) * inv * gg.z + bb.z;
    o.w = (v.w - mu) * inv * gg.w + bb.w;
    *(float4*)(O + (long)row * D_MODEL + t * 4) = o;
}

// ---------------------------------------------------------------------------
extern "C" void kernel_launch(void* const* d_in, const int* in_sizes, int n_in,
                              void* d_out, int out_size)
{
    const float* query   = (const float*)d_in[0];
    const float* ent_emb = (const float*)d_in[1];
    const int*   idx     = (const int*)  d_in[2];
    const float* WQ_w = (const float*)d_in[4];
    const float* WQ_b = (const float*)d_in[5];
    const float* WK_w = (const float*)d_in[6];
    const float* WK_b = (const float*)d_in[7];
    const float* WO_w = (const float*)d_in[8];
    const float* WO_b = (const float*)d_in[9];
    const float* ln_g = (const float*)d_in[10];
    const float* ln_b = (const float*)d_in[11];
    float* out = (float*)d_out;

    __half *qh, *Gh, *T12, *EQEO, *EOT, *Wh, *Wl;
    __half *WQTh, *WQTl, *WKTh, *WKTl, *WOh, *WOl;
    float *sb, *vb, *b2, *S, *P;
    cudaGetSymbolAddress((void**)&qh,   g_qh);
    cudaGetSymbolAddress((void**)&WQTh, g_WQTh); cudaGetSymbolAddress((void**)&WQTl, g_WQTl);
    cudaGetSymbolAddress((void**)&WKTh, g_WKTh); cudaGetSymbolAddress((void**)&WKTl, g_WKTl);
    cudaGetSymbolAddress((void**)&WOh,  g_WOh);  cudaGetSymbolAddress((void**)&WOl,  g_WOl);
    cudaGetSymbolAddress((void**)&Gh,   g_Gh);
    cudaGetSymbolAddress((void**)&T12,  g_T12);
    cudaGetSymbolAddress((void**)&EQEO, g_EQEO);
    cudaGetSymbolAddress((void**)&EOT,  g_EOT);
    cudaGetSymbolAddress((void**)&Wh,   g_Wh);   cudaGetSymbolAddress((void**)&Wl,   g_Wl);
    cudaGetSymbolAddress((void**)&sb,   g_sb);
    cudaGetSymbolAddress((void**)&vb,   g_vb);
    cudaGetSymbolAddress((void**)&b2,   g_b2);
    cudaGetSymbolAddress((void**)&S,    g_S);
    cudaGetSymbolAddress((void**)&P,    g_P);

    cudaFuncSetAttribute((const void*)gemm2<2, true >,
        cudaFuncAttributeMaxDynamicSharedMemorySize, GSMEM_A2);
    cudaFuncSetAttribute((const void*)gemm2<2, false>,
        cudaFuncAttributeMaxDynamicSharedMemorySize, GSMEM_A2);
    cudaFuncSetAttribute((const void*)gemm2<1, true >,
        cudaFuncAttributeMaxDynamicSharedMemorySize, GSMEM_A1);
    cudaFuncSetAttribute((const void*)gemm2<1, false>,
        cudaFuncAttributeMaxDynamicSharedMemorySize, GSMEM_A1);

    const int DD4 = D_MODEL * D_MODEL / 4;

    // 0. input preprocessing
    tohalf<<<(ML * D_MODEL / 4 + 255) / 256, 256>>>(query, qh, ML * D_MODEL / 4);
    split_f16<<<(DD4 + 255) / 256, 256>>>(WO_w, WOh, WOl, DD4);
    split_tr<<<dim3(32, 32), dim3(32, 8)>>>(WQ_w, WQTh, WQTl);
    split_tr<<<dim3(32, 32), dim3(32, 8)>>>(WK_w, WKTh, WKTl);
    prep_vec<<<3073, 256>>>(WQTh, WQTl, WO_w, WKTh, WKTl, WK_b, WQ_b, b2, vb);
    gather_sb<<<MB, 256>>>(ent_emb, idx, vb, Gh, sb);

    // 1. weight products (2-term fp16 A, 1-plane B): T1 = WQ^T@WK, T2 = WO@WK
    gemm2<2, true><<<dim3(8, 8, 1), 256, GSMEM_A2>>>(
        WQTh, WQTl, 0, WKTh, 0, D_MODEL, nullptr, T12, 0,
        D_MODEL, D_MODEL, nullptr, 0);
    gemm2<2, true><<<dim3(8, 8, 1), 256, GSMEM_A2>>>(
        WOh, WOl, 0, WKTh, 0, D_MODEL, nullptr, T12 + (long)1024 * D_MODEL, 0,
        D_MODEL, D_MODEL, nullptr, 0);

    // 2. EQEO = G @ [T1;T2]^T + bias2   [4096 x 2048 x 1024], 1-term A, fp16 out
    gemm2<1, true><<<dim3(16, 32, 1), 256, GSMEM_A1>>>(
        Gh, nullptr, 0, T12, 0, D_MODEL, nullptr, EQEO, 0,
        2048, D_MODEL, b2, 0);

    // 3. S[b] = query[b] @ EQ[b]^T + sb[b]   (1-term A)
    gemm2<1, false><<<dim3(2, 8, BATCH), 256, GSMEM_A1>>>(
        qh, nullptr, (long)LQ * D_MODEL, EQEO, (long)NBE * 2048, 2048,
        S, nullptr, (long)LQ * NBE, NBE, D_MODEL, sb, NBE);

    // 4. masked softmax + d^-0.5 -> fp16 planes
    softmax_split<<<ML, NBE>>>(S, idx, Wh, Wl);

    // 5. EOT[b] = EO[b]^T
    transpose_f16<<<dim3(32, 8, BATCH), dim3(32, 8)>>>(EQEO, EOT);

    // 6. P[b] = W[b] @ EOT[b]^T + bO   (2-term A protects the output)
    gemm2<2, false><<<dim3(8, 8, BATCH), 256, GSMEM_A2>>>(
        Wh, Wl, (long)LQ * NBE, EOT, (long)D_MODEL * NBE, NBE,
        P, nullptr, (long)LQ * D_MODEL, D_MODEL, NBE, WO_b, 0);

    // 7. LayerNorm -> out
    layernorm_k<<<ML, 256>>>(P, ln_g, ln_b, out);
}

// round 11
// speedup vs baseline: 2.1189x; 1.2191x over previous
#include <cuda_runtime.h>
#include <cuda_bf16.h>
#include <cuda_fp16.h>
#include <cstdint>

// ---------------------------------------------------------------------------
// Problem constants
// ---------------------------------------------------------------------------
#define D_MODEL 1024
#define BATCH   16
#define LQ      1024
#define NBE     256
#define ML (BATCH * LQ)    // 16384
#define MB (BATCH * NBE)   // 4096

// ---------------------------------------------------------------------------
// Scratch (__device__ globals; no allocation anywhere)
// ---------------------------------------------------------------------------
__device__ __half  g_qh  [ML * D_MODEL];                 // query fp16 (1 plane)
__device__ __half  g_A12h[2048 * D_MODEL];               // [WQ^T ; WO] hi plane
__device__ __half  g_A12l[2048 * D_MODEL];               // [WQ^T ; WO] lo plane
__device__ __half  g_WKTh[D_MODEL * D_MODEL];            // WK^T hi
__device__ __half  g_WKTl[D_MODEL * D_MODEL];            // WK^T lo
__device__ __half  g_Gh  [MB * D_MODEL];                 // gathered ents (1 plane)
__device__ __half  g_T12 [2048 * D_MODEL];               // [T1; T2] fp16
__device__ __half  g_EQEO[MB * 2048];                    // [EQ | EO] fp16
__device__ __half  g_EOT [MB * D_MODEL];                 // EO^T per batch
__device__ float   g_sb  [MB];                           // bQ.ENT score bias
__device__ float   g_vb  [1025];                         // WK^T bQ, [1024]=bQ.bK
__device__ float   g_b2  [2048];                         // [bK@WQ | bK@WO^T]
__device__ float   g_S   [ML * NBE];                     // scores fp32
__device__ __half  g_Wh  [ML * NBE];                     // softmax wts fp16 (1 plane)
__device__ float   g_P   [ML * D_MODEL];                 // pre-LN fp32

// ---------------------------------------------------------------------------
// Helpers
// ---------------------------------------------------------------------------
__device__ __forceinline__ void split1h(float x, __half& h, __half& l) {
    h = __float2half_rn(x);
    l = __float2half_rn(x - __half2float(h));
}

__device__ __forceinline__ void cp16(uint32_t dst, const void* src) {
    asm volatile("cp.async.cg.shared.global [%0], [%1], 16;"
                 :: "r"(dst), "l"(src) : "memory");
}
__device__ __forceinline__ void ldsm4(uint32_t* r, uint32_t addr) {
    asm volatile("ldmatrix.sync.aligned.m8n8.x4.shared.b16 {%0,%1,%2,%3}, [%4];"
                 : "=r"(r[0]), "=r"(r[1]), "=r"(r[2]), "=r"(r[3]) : "r"(addr));
}
__device__ __forceinline__ void mma_f16(float* c, const uint32_t* a,
                                        uint32_t b0, uint32_t b1) {
    asm volatile(
        "mma.sync.aligned.m16n8k16.row.col.f32.f16.f16.f32 "
        "{%0,%1,%2,%3}, {%4,%5,%6,%7}, {%8,%9}, {%0,%1,%2,%3};"
        : "+f"(c[0]), "+f"(c[1]), "+f"(c[2]), "+f"(c[3])
        : "r"(a[0]), "r"(a[1]), "r"(a[2]), "r"(a[3]), "r"(b0), "r"(b1));
}

#define BKC 32
#define SKB 80                        // smem row stride bytes (40 halves)
#define PLANE_B (128 * SKB)           // 10240 B per plane per stage

// ---------------------------------------------------------------------------
// gemm2: fp16 NT GEMM: C[bz][M,N] = (Ah (+Al)) @ B^T (+bias)
// A ATERMS fp16 planes (lda=K), B single fp16 plane (row stride ldb).
// Output fp16 (F16OUT) or fp32.  bias[bz*sBias + col].
// CTA 128x128, BK=32, 8 warps (2x4, warp tile 64x32),
// 2-stage cp.async pipeline, 256 threads, 2 CTAs/SM.
// ---------------------------------------------------------------------------
template<int ATERMS, bool F16OUT>
__global__ void __launch_bounds__(256, 2) gemm2(
    const __half* __restrict__ Ahp, const __half* __restrict__ Alp, long sA,
    const __half* __restrict__ Bp, long sB, int ldb,
    float* __restrict__ Cf, __half* __restrict__ Ch, long sC,
    int N, int K,
    const float* __restrict__ bias, long sBias)
{
    constexpr int PLANES  = ATERMS + 1;
    constexpr int STAGE_B = PLANES * PLANE_B;
    constexpr int BOFF    = ATERMS * PLANE_B;

    extern __shared__ char smc[];
    const uint32_t smb = (uint32_t)__cvta_generic_to_shared(smc);

    const int tid  = threadIdx.x;
    const int wid  = tid >> 5;
    const int lane = tid & 31;
    const int wm   = wid >> 2;
    const int wn   = wid & 3;
    const int gq   = lane >> 2;
    const int tg   = lane & 3;

    const int mtile = blockIdx.y * 128;
    const int ntile = blockIdx.x * 128;
    const int bz    = blockIdx.z;
    Ahp += (long)bz * sA;
    if (ATERMS == 2) Alp += (long)bz * sA;
    Bp  += (long)bz * sB;

    const int nch = K >> 5;

    float acc[4][4][4];
#pragma unroll
    for (int i = 0; i < 4; i++)
#pragma unroll
        for (int j = 0; j < 4; j++)
#pragma unroll
            for (int q = 0; q < 4; q++) acc[i][j][q] = 0.f;

    const int lrow = tid >> 2;
    const int lseg = tid & 3;
    const long aoff = (long)(mtile + lrow) * K + lseg * 8;
    const long boff = (long)(ntile + lrow) * ldb + lseg * 8;
    const long ahalf = (long)64 * K;
    const long bhalf = (long)64 * ldb;
    const uint32_t sdst = lrow * SKB + lseg * 16;
    const uint32_t shalf = 64 * SKB;

    auto load_chunk = [&](int c, int s) {
        const long kofs = (long)c * BKC;
        const uint32_t sb = smb + s * STAGE_B + sdst;
        cp16(sb,               Ahp + aoff + kofs);
        cp16(sb + shalf,       Ahp + aoff + ahalf + kofs);
        if (ATERMS == 2) {
            cp16(sb + PLANE_B,          Alp + aoff + kofs);
            cp16(sb + PLANE_B + shalf,  Alp + aoff + ahalf + kofs);
        }
        cp16(sb + BOFF,         Bp + boff + kofs);
        cp16(sb + BOFF + shalf, Bp + boff + bhalf + kofs);
    };

    load_chunk(0, 0);
    asm volatile("cp.async.commit_group;" ::: "memory");

    const int lr = (lane & 7) + ((lane >> 3) & 1) * 8;
    const int lc = ((lane >> 4) & 1) * 16;

    for (int c = 0; c < nch; c++) {
        const int s = c & 1;
        if (c + 1 < nch) {
            load_chunk(c + 1, s ^ 1);
            asm volatile("cp.async.commit_group;" ::: "memory");
            asm volatile("cp.async.wait_group 1;" ::: "memory");
        } else {
            asm volatile("cp.async.wait_group 0;" ::: "memory");
        }
        __syncthreads();
        const uint32_t stb = smb + s * STAGE_B;

#pragma unroll
        for (int kk = 0; kk < 2; kk++) {
            uint32_t bh[2][4];
#pragma unroll
            for (int h = 0; h < 2; h++) {
                uint32_t bd = stb + BOFF
                            + (uint32_t)(wn * 32 + h * 16 + lr) * SKB + kk * 32 + lc;
                ldsm4(bh[h], bd);
            }
#pragma unroll
            for (int mp = 0; mp < 2; mp++) {
                uint32_t ah[2][4], al[2][4];
#pragma unroll
                for (int m2 = 0; m2 < 2; m2++) {
                    uint32_t ad = stb
                        + (uint32_t)(wm * 64 + (mp * 2 + m2) * 16 + lr) * SKB
                        + kk * 32 + lc;
                    ldsm4(ah[m2], ad);
                    if (ATERMS == 2) ldsm4(al[m2], ad + PLANE_B);
                }
#pragma unroll
                for (int m2 = 0; m2 < 2; m2++)
#pragma unroll
                    for (int h = 0; h < 2; h++)
#pragma unroll
                        for (int j = 0; j < 2; j++) {
                            float* cc = acc[mp * 2 + m2][h * 2 + j];
                            mma_f16(cc, ah[m2], bh[h][j], bh[h][j + 2]);
                            if (ATERMS == 2)
                                mma_f16(cc, al[m2], bh[h][j], bh[h][j + 2]);
                        }
            }
        }
        __syncthreads();
    }

#pragma unroll
    for (int mt = 0; mt < 4; mt++) {
        const int r0 = mtile + wm * 64 + mt * 16 + gq;
#pragma unroll
        for (int nt = 0; nt < 4; nt++) {
            const int col = ntile + wn * 32 + nt * 8 + tg * 2;
            float bx = 0.f, by = 0.f;
            if (bias != nullptr) {
                float2 bb = *(const float2*)(bias + bz * sBias + col);
                bx = bb.x; by = bb.y;
            }
            float o00 = acc[mt][nt][0] + bx;
            float o01 = acc[mt][nt][1] + by;
            float o10 = acc[mt][nt][2] + bx;
            float o11 = acc[mt][nt][3] + by;
            const long i0 = (long)bz * sC + (long)r0 * N + col;
            const long i1 = i0 + (long)8 * N;
            if (F16OUT) {
                __half2 p0, p1;
                p0.x = __float2half_rn(o00); p0.y = __float2half_rn(o01);
                p1.x = __float2half_rn(o10); p1.y = __float2half_rn(o11);
                *(__half2*)(Ch + i0) = p0;
                *(__half2*)(Ch + i1) = p1;
            } else {
                *(float2*)(Cf + i0) = make_float2(o00, o01);
                *(float2*)(Cf + i1) = make_float2(o10, o11);
            }
        }
    }
}

#define GSMEM_A2 (2 * 3 * PLANE_B)    // 61440
#define GSMEM_A1 (2 * 2 * PLANE_B)    // 40960

// ---------------------------------------------------------------------------
// query fp32 -> single fp16 plane (RN)
// ---------------------------------------------------------------------------
__global__ void tohalf(const float* __restrict__ x, __half* __restrict__ h, int n4)
{
    int i = blockIdx.x * blockDim.x + threadIdx.x;
    if (i >= n4) return;
    float4 v = ((const float4*)x)[i];
    __half hh[4];
    hh[0] = __float2half_rn(v.x); hh[1] = __float2half_rn(v.y);
    hh[2] = __float2half_rn(v.z); hh[3] = __float2half_rn(v.w);
    ((uint2*)h)[i] = *(uint2*)hh;
}

// fp32 -> fp16 hi/lo split (WO, into the stacked A12 arrays at row 1024)
__global__ void split_f16(const float* __restrict__ x,
                          __half* __restrict__ h, __half* __restrict__ l, int n4)
{
    int i = blockIdx.x * blockDim.x + threadIdx.x;
    if (i >= n4) return;
    float4 v = ((const float4*)x)[i];
    __half hh[4], ll[4];
    split1h(v.x, hh[0], ll[0]); split1h(v.y, hh[1], ll[1]);
    split1h(v.z, hh[2], ll[2]); split1h(v.w, hh[3], ll[3]);
    ((uint2*)h)[i] = *(uint2*)hh;
    ((uint2*)l)[i] = *(uint2*)ll;
}

// split + transpose (D,D) fp32 -> fp16 planes of W^T  (CLOCK CANARY kernel)
__global__ void split_tr(const float* __restrict__ W,
                         __half* __restrict__ Th, __half* __restrict__ Tl)
{
    __shared__ float t[32][33];
    const int c0 = blockIdx.x * 32;
    const int r0 = blockIdx.y * 32;
    const int tx = threadIdx.x, ty = threadIdx.y;
#pragma unroll
    for (int i = 0; i < 32; i += 8)
        t[ty + i][tx] = W[(long)(r0 + ty + i) * D_MODEL + c0 + tx];
    __syncthreads();
#pragma unroll
    for (int i = 0; i < 32; i += 8) {
        float v = t[tx][ty + i];
        __half h, l;
        split1h(v, h, l);
        const long o = (long)(c0 + ty + i) * D_MODEL + r0 + tx;
        Th[o] = h;  Tl[o] = l;
    }
}

// ---------------------------------------------------------------------------
// prep_vec: b2[0:1024]=bK@WQ, b2[1024:2048]=bK@WO^T, vb[0:1024]=WK^T bQ,
// vb[1024]=bQ.bK.  One block per output element.
// WQT = A12 rows 0..1023; WO fp32 original.
// ---------------------------------------------------------------------------
__global__ void prep_vec(const __half* __restrict__ A12h,
                         const __half* __restrict__ A12l,
                         const float* __restrict__ WO,
                         const __half* __restrict__ WKTh,
                         const __half* __restrict__ WKTl,
                         const float* __restrict__ bK,
                         const float* __restrict__ bQ,
                         float* __restrict__ b2, float* __restrict__ vb)
{
    const int n = blockIdx.x;
    const int t = threadIdx.x;
    float s = 0.f;

    if (n < 1024) {
        const uint2 h2 = ((const uint2*)(A12h + (long)n * D_MODEL))[t];
        const uint2 l2 = ((const uint2*)(A12l + (long)n * D_MODEL))[t];
        const __half* hp = (const __half*)&h2;
        const __half* lp = (const __half*)&l2;
        float4 b = ((const float4*)bK)[t];
        s = (__half2float(hp[0]) + __half2float(lp[0])) * b.x
          + (__half2float(hp[1]) + __half2float(lp[1])) * b.y
          + (__half2float(hp[2]) + __half2float(lp[2])) * b.z
          + (__half2float(hp[3]) + __half2float(lp[3])) * b.w;
    } else if (n < 2048) {
        float4 w = ((const float4*)(WO + (long)(n - 1024) * D_MODEL))[t];
        float4 b = ((const float4*)bK)[t];
        s = w.x * b.x + w.y * b.y + w.z * b.z + w.w * b.w;
    } else if (n < 3072) {
        const uint2 h2 = ((const uint2*)(WKTh + (long)(n - 2048) * D_MODEL))[t];
        const uint2 l2 = ((const uint2*)(WKTl + (long)(n - 2048) * D_MODEL))[t];
        const __half* hp = (const __half*)&h2;
        const __half* lp = (const __half*)&l2;
        float4 b = ((const float4*)bQ)[t];
        s = (__half2float(hp[0]) + __half2float(lp[0])) * b.x
          + (__half2float(hp[1]) + __half2float(lp[1])) * b.y
          + (__half2float(hp[2]) + __half2float(lp[2])) * b.z
          + (__half2float(hp[3]) + __half2float(lp[3])) * b.w;
    } else {
        float4 q = ((const float4*)bQ)[t];
        float4 b = ((const float4*)bK)[t];
        s = q.x * b.x + q.y * b.y + q.z * b.z + q.w * b.w;
    }

    __shared__ float red[8];
#pragma unroll
    for (int o = 16; o; o >>= 1) s += __shfl_xor_sync(0xffffffffu, s, o);
    if ((t & 31) == 0) red[t >> 5] = s;
    __syncthreads();
    if (t == 0) {
        float tot = 0.f;
#pragma unroll
        for (int i = 0; i < 8; i++) tot += red[i];
        if (n < 2048)      b2[n] = tot;
        else if (n < 3072) vb[n - 2048] = tot;
        else               vb[1024] = tot;
    }
}

// ---------------------------------------------------------------------------
// gather (single fp16 plane) + score-bias: G[r]=rn(E[max(idx,0)]),
// sb[r] = E_r . v + bQ.bK
// ---------------------------------------------------------------------------
__global__ void gather_sb(const float* __restrict__ E,
                          const int* __restrict__ idx,
                          const float* __restrict__ vb,
                          __half* __restrict__ Gh,
                          float* __restrict__ sb)
{
    const int r = blockIdx.x;
    int s = idx[r];
    if (s < 0) s = 0;
    const int i = threadIdx.x;
    float4 v = ((const float4*)(E + (long)s * D_MODEL))[i];
    __half hh[4];
    hh[0] = __float2half_rn(v.x); hh[1] = __float2half_rn(v.y);
    hh[2] = __float2half_rn(v.z); hh[3] = __float2half_rn(v.w);
    ((uint2*)(Gh + (long)r * D_MODEL))[i] = *(uint2*)hh;

    float4 w = ((const float4*)vb)[i];
    float d = v.x * w.x + v.y * w.y + v.z * w.z + v.w * w.w;
    __shared__ float red[8];
#pragma unroll
    for (int o = 16; o; o >>= 1) d += __shfl_xor_sync(0xffffffffu, d, o);
    if ((i & 31) == 0) red[i >> 5] = d;
    __syncthreads();
    if (i == 0) {
        float tot = vb[1024];
#pragma unroll
        for (int k = 0; k < 8; k++) tot += red[k];
        sb[r] = tot;
    }
}

// ---------------------------------------------------------------------------
// per-batch fp16 transpose of the EO half of EQEO -> EOT[b] (D x NBE)
// ---------------------------------------------------------------------------
__global__ void transpose_f16(const __half* __restrict__ EQEO,
                              __half* __restrict__ EOT)
{
    __shared__ __half t[32][34];
    const int b  = blockIdx.z;
    const int c0 = blockIdx.x * 32;
    const int r0 = blockIdx.y * 32;
    const int tx = threadIdx.x, ty = threadIdx.y;
#pragma unroll
    for (int i = 0; i < 32; i += 8)
        t[ty + i][tx] = EQEO[(long)(b * NBE + r0 + ty + i) * 2048 + 1024 + c0 + tx];
    __syncthreads();
#pragma unroll
    for (int i = 0; i < 32; i += 8)
        EOT[(long)b * NBE * D_MODEL + (long)(c0 + ty + i) * NBE + r0 + tx]
            = t[tx][ty + i];
}

// ---------------------------------------------------------------------------
// masked softmax over NB=256 + d^-0.5 scale -> single fp16 plane
// ---------------------------------------------------------------------------
__global__ void softmax_h(const float* __restrict__ S,
                          const int* __restrict__ idx,
                          __half* __restrict__ Wh)
{
    const int row = blockIdx.x;
    const int b   = row >> 10;
    const int n   = threadIdx.x;
    const long off = (long)row * NBE + n;

    float s = S[off];
    if (idx[b * NBE + n] < 0) s = -100000.0f;

    __shared__ float red[8];
    float m = s;
#pragma unroll
    for (int o = 16; o; o >>= 1) m = fmaxf(m, __shfl_xor_sync(0xffffffffu, m, o));
    if ((n & 31) == 0) red[n >> 5] = m;
    __syncthreads();
    float mall = red[0];
#pragma unroll
    for (int i = 1; i < 8; i++) mall = fmaxf(mall, red[i]);

    float e = expf(s - mall);
    __syncthreads();
    float t = e;
#pragma unroll
    for (int o = 16; o; o >>= 1) t += __shfl_xor_sync(0xffffffffu, t, o);
    if ((n & 31) == 0) red[n >> 5] = t;
    __syncthreads();
    float sum = 0.f;
#pragma unroll
    for (int i = 0; i < 8; i++) sum += red[i];

    Wh[off] = __float2half_rn(e * (0.03125f / sum));
}

// ---------------------------------------------------------------------------
// Row LayerNorm over D=1024 (biased var, eps=1e-5).
// ---------------------------------------------------------------------------
__global__ void layernorm_k(const float* __restrict__ X,
                            const float* __restrict__ g,
                            const float* __restrict__ b,
                            float* __restrict__ O)
{
    const int row = blockIdx.x;
    const int t   = threadIdx.x;
    const float* x = X + (long)row * D_MODEL;

    float4 v = *(const float4*)(x + t * 4);
    float s  = v.x + v.y + v.z + v.w;
    float sq = v.x * v.x + v.y * v.y + v.z * v.z + v.w * v.w;

    __shared__ float rs[8], rq[8];
#pragma unroll
    for (int o = 16; o; o >>= 1) {
        s  += __shfl_xor_sync(0xffffffffu, s,  o);
        sq += __shfl_xor_sync(0xffffffffu, sq, o);
    }
    if ((t & 31) == 0) { rs[t >> 5] = s; rq[t >> 5] = sq; }
    __syncthreads();
    float S = 0.f, Q = 0.f;
#pragma unroll
    for (int i = 0; i < 8; i++) { S += rs[i]; Q += rq[i]; }

    float mu  = S * (1.f / 1024.f);
    float var = Q * (1.f / 1024.f) - mu * mu;
    float inv = rsqrtf(var + 1e-5f);

    float4 gg = *(const float4*)(g + t * 4);
    float4 bb = *(const float4*)(b + t * 4);
    float4 o;
    o.x = (v.x - mu) * inv * gg.x + bb.x;
    o.y = (v.y - mu) * inv * gg.y + bb.y;
    o.z = (v.z - mu) * inv * gg.z + bb.z;
    o.w = (v.w - mu) * inv * gg.w + bb.w;
    *(float4*)(O + (long)row * D_MODEL + t * 4) = o;
}

// ---------------------------------------------------------------------------
extern "C" void kernel_launch(void* const* d_in, const int* in_sizes, int n_in,
                              void* d_out, int out_size)
{
    const float* query   = (const float*)d_in[0];
    const float* ent_emb = (const float*)d_in[1];
    const int*   idx     = (const int*)  d_in[2];
    const float* WQ_w = (const float*)d_in[4];
    const float* WQ_b = (const float*)d_in[5];
    const float* WK_w = (const float*)d_in[6];
    const float* WK_b = (const float*)d_in[7];
    const float* WO_w = (const float*)d_in[8];
    const float* WO_b = (const float*)d_in[9];
    const float* ln_g = (const float*)d_in[10];
    const float* ln_b = (const float*)d_in[11];
    float* out = (float*)d_out;

    __half *qh, *A12h, *A12l, *WKTh, *WKTl, *Gh, *T12, *EQEO, *EOT, *Wh;
    float *sb, *vb, *b2, *S, *P;
    cudaGetSymbolAddress((void**)&qh,   g_qh);
    cudaGetSymbolAddress((void**)&A12h, g_A12h); cudaGetSymbolAddress((void**)&A12l, g_A12l);
    cudaGetSymbolAddress((void**)&WKTh, g_WKTh); cudaGetSymbolAddress((void**)&WKTl, g_WKTl);
    cudaGetSymbolAddress((void**)&Gh,   g_Gh);
    cudaGetSymbolAddress((void**)&T12,  g_T12);
    cudaGetSymbolAddress((void**)&EQEO, g_EQEO);
    cudaGetSymbolAddress((void**)&EOT,  g_EOT);
    cudaGetSymbolAddress((void**)&Wh,   g_Wh);
    cudaGetSymbolAddress((void**)&sb,   g_sb);
    cudaGetSymbolAddress((void**)&vb,   g_vb);
    cudaGetSymbolAddress((void**)&b2,   g_b2);
    cudaGetSymbolAddress((void**)&S,    g_S);
    cudaGetSymbolAddress((void**)&P,    g_P);

    cudaFuncSetAttribute((const void*)gemm2<2, true >,
        cudaFuncAttributeMaxDynamicSharedMemorySize, GSMEM_A2);
    cudaFuncSetAttribute((const void*)gemm2<1, true >,
        cudaFuncAttributeMaxDynamicSharedMemorySize, GSMEM_A1);
    cudaFuncSetAttribute((const void*)gemm2<1, false>,
        cudaFuncAttributeMaxDynamicSharedMemorySize, GSMEM_A1);

    const int DD4 = D_MODEL * D_MODEL / 4;
    const long DD = (long)D_MODEL * D_MODEL;

    // 0. input preprocessing
    tohalf<<<(ML * D_MODEL / 4 + 255) / 256, 256>>>(query, qh, ML * D_MODEL / 4);
    // A12 rows 0..1023 = WQ^T (split+transpose); rows 1024..2047 = WO (split)
    split_tr<<<dim3(32, 32), dim3(32, 8)>>>(WQ_w, A12h, A12l);
    split_f16<<<(DD4 + 255) / 256, 256>>>(WO_w, A12h + DD, A12l + DD, DD4);
    split_tr<<<dim3(32, 32), dim3(32, 8)>>>(WK_w, WKTh, WKTl);
    prep_vec<<<3073, 256>>>(A12h, A12l, WO_w, WKTh, WKTl, WK_b, WQ_b, b2, vb);
    gather_sb<<<MB, 256>>>(ent_emb, idx, vb, Gh, sb);

    // 1. merged weight product: [T1;T2] = [WQ^T;WO] @ WK  (2-term A, one GEMM)
    gemm2<2, true><<<dim3(8, 16, 1), 256, GSMEM_A2>>>(
        A12h, A12l, 0, WKTh, 0, D_MODEL, nullptr, T12, 0,
        D_MODEL, D_MODEL, nullptr, 0);

    // 2. EQEO = G @ [T1;T2]^T + bias2   [4096 x 2048 x 1024], 1-term A
    gemm2<1, true><<<dim3(16, 32, 1), 256, GSMEM_A1>>>(
        Gh, nullptr, 0, T12, 0, D_MODEL, nullptr, EQEO, 0,
        2048, D_MODEL, b2, 0);

    // 3. S[b] = query[b] @ EQ[b]^T + sb[b]   (1-term A)
    gemm2<1, false><<<dim3(2, 8, BATCH), 256, GSMEM_A1>>>(
        qh, nullptr, (long)LQ * D_MODEL, EQEO, (long)NBE * 2048, 2048,
        S, nullptr, (long)LQ * NBE, NBE, D_MODEL, sb, NBE);

    // 4. masked softmax + d^-0.5 -> single fp16 plane
    softmax_h<<<ML, NBE>>>(S, idx, Wh);

    // 5. EOT[b] = EO[b]^T
    transpose_f16<<<dim3(32, 8, BATCH), dim3(32, 8)>>>(EQEO, EOT);

    // 6. P[b] = W[b] @ EOT[b]^T + bO   (1-term A)
    gemm2<1, false><<<dim3(8, 8, BATCH), 256, GSMEM_A1>>>(
        Wh, nullptr, (long)LQ * NBE, EOT, (long)D_MODEL * NBE, NBE,
        P, nullptr, (long)LQ * D_MODEL, D_MODEL, NBE, WO_b, 0);

    // 7. LayerNorm -> out
    layernorm_k<<<ML, 256>>>(P, ln_g, ln_b, out);
}

// round 12
// speedup vs baseline: 2.2093x; 1.0427x over previous
#include <cuda_runtime.h>
#include <cuda_bf16.h>
#include <cuda_fp16.h>
#include <cstdint>

// ---------------------------------------------------------------------------
// Problem constants
// ---------------------------------------------------------------------------
#define D_MODEL 1024
#define BATCH   16
#define LQ      1024
#define NBE     256
#define ML (BATCH * LQ)    // 16384
#define MB (BATCH * NBE)   // 4096

// ---------------------------------------------------------------------------
// Scratch (__device__ globals; no allocation anywhere)
// ---------------------------------------------------------------------------
__device__ __half  g_qh  [ML * D_MODEL];                 // query fp16 (1 plane)
__device__ __half  g_A12h[2048 * D_MODEL];               // [WQ^T ; WO] hi plane
__device__ __half  g_A12l[2048 * D_MODEL];               // [WQ^T ; WO] lo plane
__device__ __half  g_WKTh[D_MODEL * D_MODEL];            // WK^T hi
__device__ __half  g_WKTl[D_MODEL * D_MODEL];            // WK^T lo
__device__ __half  g_Gh  [MB * D_MODEL];                 // gathered ents (1 plane)
__device__ __half  g_T12 [2048 * D_MODEL];               // [T1; T2] fp16
__device__ __half  g_EQEO[MB * 2048];                    // [EQ | EO] fp16
__device__ __half  g_EOT [MB * D_MODEL];                 // EO^T per batch
__device__ float   g_sb  [MB];                           // bQ.ENT score bias
__device__ float   g_vb  [1025];                         // WK^T bQ, [1024]=bQ.bK
__device__ float   g_b2  [2048];                         // [bK@WQ | bK@WO^T]
__device__ __half  g_Wh  [ML * NBE];                     // softmax wts fp16 (1 plane)
__device__ float   g_P   [ML * D_MODEL];                 // pre-LN fp32

// ---------------------------------------------------------------------------
// Helpers
// ---------------------------------------------------------------------------
__device__ __forceinline__ void split1h(float x, __half& h, __half& l) {
    h = __float2half_rn(x);
    l = __float2half_rn(x - __half2float(h));
}

__device__ __forceinline__ void cp16(uint32_t dst, const void* src) {
    asm volatile("cp.async.cg.shared.global [%0], [%1], 16;"
                 :: "r"(dst), "l"(src) : "memory");
}
__device__ __forceinline__ void ldsm4(uint32_t* r, uint32_t addr) {
    asm volatile("ldmatrix.sync.aligned.m8n8.x4.shared.b16 {%0,%1,%2,%3}, [%4];"
                 : "=r"(r[0]), "=r"(r[1]), "=r"(r[2]), "=r"(r[3]) : "r"(addr));
}
__device__ __forceinline__ void mma_f16(float* c, const uint32_t* a,
                                        uint32_t b0, uint32_t b1) {
    asm volatile(
        "mma.sync.aligned.m16n8k16.row.col.f32.f16.f16.f32 "
        "{%0,%1,%2,%3}, {%4,%5,%6,%7}, {%8,%9}, {%0,%1,%2,%3};"
        : "+f"(c[0]), "+f"(c[1]), "+f"(c[2]), "+f"(c[3])
        : "r"(a[0]), "r"(a[1]), "r"(a[2]), "r"(a[3]), "r"(b0), "r"(b1));
}

#define BKC 32
#define SKB 80                        // smem row stride bytes (40 halves)
#define PLANE_B (128 * SKB)           // 10240 B per plane per stage

// ---------------------------------------------------------------------------
// gemm2: fp16 NT GEMM: C[bz][M,N] = (Ah (+Al)) @ B^T (+bias)
// A ATERMS fp16 planes (lda=K), B single fp16 plane (row stride ldb).
// Output fp16 (F16OUT) or fp32.  bias[bz*sBias + col].
// CTA 128x128, BK=32, 8 warps (2x4, warp tile 64x32),
// 2-stage cp.async pipeline, 256 threads, 2 CTAs/SM.
// ---------------------------------------------------------------------------
template<int ATERMS, bool F16OUT>
__global__ void __launch_bounds__(256, 2) gemm2(
    const __half* __restrict__ Ahp, const __half* __restrict__ Alp, long sA,
    const __half* __restrict__ Bp, long sB, int ldb,
    float* __restrict__ Cf, __half* __restrict__ Ch, long sC,
    int N, int K,
    const float* __restrict__ bias, long sBias)
{
    constexpr int PLANES  = ATERMS + 1;
    constexpr int STAGE_B = PLANES * PLANE_B;
    constexpr int BOFF    = ATERMS * PLANE_B;

    extern __shared__ char smc[];
    const uint32_t smb = (uint32_t)__cvta_generic_to_shared(smc);

    const int tid  = threadIdx.x;
    const int wid  = tid >> 5;
    const int lane = tid & 31;
    const int wm   = wid >> 2;
    const int wn   = wid & 3;
    const int gq   = lane >> 2;
    const int tg   = lane & 3;

    const int mtile = blockIdx.y * 128;
    const int ntile = blockIdx.x * 128;
    const int bz    = blockIdx.z;
    Ahp += (long)bz * sA;
    if (ATERMS == 2) Alp += (long)bz * sA;
    Bp  += (long)bz * sB;

    const int nch = K >> 5;

    float acc[4][4][4];
#pragma unroll
    for (int i = 0; i < 4; i++)
#pragma unroll
        for (int j = 0; j < 4; j++)
#pragma unroll
            for (int q = 0; q < 4; q++) acc[i][j][q] = 0.f;

    const int lrow = tid >> 2;
    const int lseg = tid & 3;
    const long aoff = (long)(mtile + lrow) * K + lseg * 8;
    const long boff = (long)(ntile + lrow) * ldb + lseg * 8;
    const long ahalf = (long)64 * K;
    const long bhalf = (long)64 * ldb;
    const uint32_t sdst = lrow * SKB + lseg * 16;
    const uint32_t shalf = 64 * SKB;

    auto load_chunk = [&](int c, int s) {
        const long kofs = (long)c * BKC;
        const uint32_t sb = smb + s * STAGE_B + sdst;
        cp16(sb,               Ahp + aoff + kofs);
        cp16(sb + shalf,       Ahp + aoff + ahalf + kofs);
        if (ATERMS == 2) {
            cp16(sb + PLANE_B,          Alp + aoff + kofs);
            cp16(sb + PLANE_B + shalf,  Alp + aoff + ahalf + kofs);
        }
        cp16(sb + BOFF,         Bp + boff + kofs);
        cp16(sb + BOFF + shalf, Bp + boff + bhalf + kofs);
    };

    load_chunk(0, 0);
    asm volatile("cp.async.commit_group;" ::: "memory");

    const int lr = (lane & 7) + ((lane >> 3) & 1) * 8;
    const int lc = ((lane >> 4) & 1) * 16;

    for (int c = 0; c < nch; c++) {
        const int s = c & 1;
        if (c + 1 < nch) {
            load_chunk(c + 1, s ^ 1);
            asm volatile("cp.async.commit_group;" ::: "memory");
            asm volatile("cp.async.wait_group 1;" ::: "memory");
        } else {
            asm volatile("cp.async.wait_group 0;" ::: "memory");
        }
        __syncthreads();
        const uint32_t stb = smb + s * STAGE_B;

#pragma unroll
        for (int kk = 0; kk < 2; kk++) {
            uint32_t bh[2][4];
#pragma unroll
            for (int h = 0; h < 2; h++) {
                uint32_t bd = stb + BOFF
                            + (uint32_t)(wn * 32 + h * 16 + lr) * SKB + kk * 32 + lc;
                ldsm4(bh[h], bd);
            }
#pragma unroll
            for (int mp = 0; mp < 2; mp++) {
                uint32_t ah[2][4], al[2][4];
#pragma unroll
                for (int m2 = 0; m2 < 2; m2++) {
                    uint32_t ad = stb
                        + (uint32_t)(wm * 64 + (mp * 2 + m2) * 16 + lr) * SKB
                        + kk * 32 + lc;
                    ldsm4(ah[m2], ad);
                    if (ATERMS == 2) ldsm4(al[m2], ad + PLANE_B);
                }
#pragma unroll
                for (int m2 = 0; m2 < 2; m2++)
#pragma unroll
                    for (int h = 0; h < 2; h++)
#pragma unroll
                        for (int j = 0; j < 2; j++) {
                            float* cc = acc[mp * 2 + m2][h * 2 + j];
                            mma_f16(cc, ah[m2], bh[h][j], bh[h][j + 2]);
                            if (ATERMS == 2)
                                mma_f16(cc, al[m2], bh[h][j], bh[h][j + 2]);
                        }
            }
        }
        __syncthreads();
    }

#pragma unroll
    for (int mt = 0; mt < 4; mt++) {
        const int r0 = mtile + wm * 64 + mt * 16 + gq;
#pragma unroll
        for (int nt = 0; nt < 4; nt++) {
            const int col = ntile + wn * 32 + nt * 8 + tg * 2;
            float bx = 0.f, by = 0.f;
            if (bias != nullptr) {
                float2 bb = *(const float2*)(bias + bz * sBias + col);
                bx = bb.x; by = bb.y;
            }
            float o00 = acc[mt][nt][0] + bx;
            float o01 = acc[mt][nt][1] + by;
            float o10 = acc[mt][nt][2] + bx;
            float o11 = acc[mt][nt][3] + by;
            const long i0 = (long)bz * sC + (long)r0 * N + col;
            const long i1 = i0 + (long)8 * N;
            if (F16OUT) {
                __half2 p0, p1;
                p0.x = __float2half_rn(o00); p0.y = __float2half_rn(o01);
                p1.x = __float2half_rn(o10); p1.y = __float2half_rn(o11);
                *(__half2*)(Ch + i0) = p0;
                *(__half2*)(Ch + i1) = p1;
            } else {
                *(float2*)(Cf + i0) = make_float2(o00, o01);
                *(float2*)(Cf + i1) = make_float2(o10, o11);
            }
        }
    }
}

#define GSMEM_A2 (2 * 3 * PLANE_B)    // 61440
#define GSMEM_A1 (2 * 2 * PLANE_B)    // 40960

// ---------------------------------------------------------------------------
// sgemm_softmax: fused scores + masked softmax.
// W[bz][64-row tile][256] = softmax_row( q[rows] @ EQ^T + sb - 1e5*mask ) * d^-0.5
// CTA tile 64 x 256 (full NB rows), 8 warps each 64x32 col slab, BK=32.
// A = qh (1 plane, lda=1024), B = EQ (rows of EQEO, ldb=2048).
// ---------------------------------------------------------------------------
#define APL_B (64 * SKB)              // 5120 B
#define BPL_B (256 * SKB)             // 20480 B
#define STG_F (APL_B + BPL_B)         // 25600 B
#define GSMEM_F (2 * STG_F)           // 51200 B

__global__ void __launch_bounds__(256, 2) sgemm_softmax(
    const __half* __restrict__ Q,      // [ML, 1024]
    const __half* __restrict__ EQEO,   // [MB, 2048], EQ = cols 0..1023
    const float* __restrict__ sb,      // [MB]
    const int* __restrict__ idx,       // [MB]
    __half* __restrict__ Wout)         // [ML, 256]
{
    extern __shared__ char smc[];
    const uint32_t smb = (uint32_t)__cvta_generic_to_shared(smc);
    __shared__ float redm[64][9];
    __shared__ float reds[64][9];

    const int tid  = threadIdx.x;
    const int wid  = tid >> 5;
    const int lane = tid & 31;
    const int gq   = lane >> 2;
    const int tg   = lane & 3;

    const int mtile = blockIdx.y * 64;
    const int bz    = blockIdx.z;
    const int K = D_MODEL, ldb = 2048;

    const __half* A = Q    + (long)bz * LQ * D_MODEL;
    const __half* B = EQEO + (long)bz * NBE * 2048;

    float acc[4][4][4];
#pragma unroll
    for (int i = 0; i < 4; i++)
#pragma unroll
        for (int j = 0; j < 4; j++)
#pragma unroll
            for (int q = 0; q < 4; q++) acc[i][j][q] = 0.f;

    // loader: A 64 rows x 4 segs = 256 slots (1/thread);
    //         B 256 rows x 4 segs = 1024 slots (4/thread, rows +64 apart)
    const int lrow = tid >> 2;
    const int lseg = tid & 3;
    const long aoff = (long)(mtile + lrow) * K + lseg * 8;
    const long boff = (long)lrow * ldb + lseg * 8;
    const uint32_t sdst = lrow * SKB + lseg * 16;
    const uint32_t s64 = 64 * SKB;

    auto load_chunk = [&](int c, int s) {
        const long kofs = (long)c * BKC;
        const uint32_t sbs = smb + s * STG_F + sdst;
        cp16(sbs, A + aoff + kofs);
        const uint32_t bb = sbs + APL_B;
        cp16(bb,           B + boff + kofs);
        cp16(bb + s64,     B + boff + (long)64  * ldb + kofs);
        cp16(bb + 2 * s64, B + boff + (long)128 * ldb + kofs);
        cp16(bb + 3 * s64, B + boff + (long)192 * ldb + kofs);
    };

    load_chunk(0, 0);
    asm volatile("cp.async.commit_group;" ::: "memory");

    const int lr = (lane & 7) + ((lane >> 3) & 1) * 8;
    const int lc = ((lane >> 4) & 1) * 16;
    const int nch = K >> 5;

    for (int c = 0; c < nch; c++) {
        const int s = c & 1;
        if (c + 1 < nch) {
            load_chunk(c + 1, s ^ 1);
            asm volatile("cp.async.commit_group;" ::: "memory");
            asm volatile("cp.async.wait_group 1;" ::: "memory");
        } else {
            asm volatile("cp.async.wait_group 0;" ::: "memory");
        }
        __syncthreads();
        const uint32_t stb = smb + s * STG_F;

#pragma unroll
        for (int kk = 0; kk < 2; kk++) {
            uint32_t bh[2][4];
#pragma unroll
            for (int h = 0; h < 2; h++) {
                uint32_t bd = stb + APL_B
                            + (uint32_t)(wid * 32 + h * 16 + lr) * SKB + kk * 32 + lc;
                ldsm4(bh[h], bd);
            }
#pragma unroll
            for (int mp = 0; mp < 2; mp++) {
                uint32_t ah[2][4];
#pragma unroll
                for (int m2 = 0; m2 < 2; m2++) {
                    uint32_t ad = stb
                        + (uint32_t)((mp * 2 + m2) * 16 + lr) * SKB + kk * 32 + lc;
                    ldsm4(ah[m2], ad);
                }
#pragma unroll
                for (int m2 = 0; m2 < 2; m2++)
#pragma unroll
                    for (int h = 0; h < 2; h++)
#pragma unroll
                        for (int j = 0; j < 2; j++)
                            mma_f16(acc[mp * 2 + m2][h * 2 + j],
                                    ah[m2], bh[h][j], bh[h][j + 2]);
            }
        }
        __syncthreads();
    }

    // ---- fused masked softmax epilogue ----
    const float* sbb = sb + bz * NBE;
    const int*  idxb = idx + bz * NBE;

    // bias + mask
#pragma unroll
    for (int nt = 0; nt < 4; nt++) {
        const int col = wid * 32 + nt * 8 + tg * 2;
        float2 bb = *(const float2*)(sbb + col);
        bool m0 = idxb[col] < 0;
        bool m1 = idxb[col + 1] < 0;
#pragma unroll
        for (int mt = 0; mt < 4; mt++) {
            acc[mt][nt][0] = m0 ? -100000.f : acc[mt][nt][0] + bb.x;
            acc[mt][nt][1] = m1 ? -100000.f : acc[mt][nt][1] + bb.y;
            acc[mt][nt][2] = m0 ? -100000.f : acc[mt][nt][2] + bb.x;
            acc[mt][nt][3] = m1 ? -100000.f : acc[mt][nt][3] + bb.y;
        }
    }

    // row max: thread-local (8 cols) -> quad shuffle -> smem across 8 warps
#pragma unroll
    for (int mt = 0; mt < 4; mt++)
#pragma unroll
        for (int rh = 0; rh < 2; rh++) {
            float m = -3.4e38f;
#pragma unroll
            for (int nt = 0; nt < 4; nt++) {
                m = fmaxf(m, acc[mt][nt][rh * 2]);
                m = fmaxf(m, acc[mt][nt][rh * 2 + 1]);
            }
            m = fmaxf(m, __shfl_xor_sync(0xffffffffu, m, 1));
            m = fmaxf(m, __shfl_xor_sync(0xffffffffu, m, 2));
            if (tg == 0) redm[mt * 16 + rh * 8 + gq][wid] = m;
        }
    __syncthreads();

    // exp + row sum
#pragma unroll
    for (int mt = 0; mt < 4; mt++)
#pragma unroll
        for (int rh = 0; rh < 2; rh++) {
            const int rl = mt * 16 + rh * 8 + gq;
            float mall = redm[rl][0];
#pragma unroll
            for (int w = 1; w < 8; w++) mall = fmaxf(mall, redm[rl][w]);
            float ssum = 0.f;
#pragma unroll
            for (int nt = 0; nt < 4; nt++) {
                float e0 = expf(acc[mt][nt][rh * 2]     - mall);
                float e1 = expf(acc[mt][nt][rh * 2 + 1] - mall);
                acc[mt][nt][rh * 2]     = e0;
                acc[mt][nt][rh * 2 + 1] = e1;
                ssum += e0 + e1;
            }
            ssum += __shfl_xor_sync(0xffffffffu, ssum, 1);
            ssum += __shfl_xor_sync(0xffffffffu, ssum, 2);
            if (tg == 0) reds[rl][wid] = ssum;
        }
    __syncthreads();

    // normalize * d^-0.5 and store fp16
#pragma unroll
    for (int mt = 0; mt < 4; mt++)
#pragma unroll
        for (int rh = 0; rh < 2; rh++) {
            const int rl = mt * 16 + rh * 8 + gq;
            float sum = reds[rl][0];
#pragma unroll
            for (int w = 1; w < 8; w++) sum += reds[rl][w];
            const float inv = 0.03125f / sum;
            const long rowoff = (long)(bz * LQ + mtile + rl) * NBE;
#pragma unroll
            for (int nt = 0; nt < 4; nt++) {
                const int col = wid * 32 + nt * 8 + tg * 2;
                __half2 p;
                p.x = __float2half_rn(acc[mt][nt][rh * 2]     * inv);
                p.y = __float2half_rn(acc[mt][nt][rh * 2 + 1] * inv);
                *(__half2*)(Wout + rowoff + col) = p;
            }
        }
}

// ---------------------------------------------------------------------------
// query fp32 -> single fp16 plane (RN)
// ---------------------------------------------------------------------------
__global__ void tohalf(const float* __restrict__ x, __half* __restrict__ h, int n4)
{
    int i = blockIdx.x * blockDim.x + threadIdx.x;
    if (i >= n4) return;
    float4 v = ((const float4*)x)[i];
    __half hh[4];
    hh[0] = __float2half_rn(v.x); hh[1] = __float2half_rn(v.y);
    hh[2] = __float2half_rn(v.z); hh[3] = __float2half_rn(v.w);
    ((uint2*)h)[i] = *(uint2*)hh;
}

// fp32 -> fp16 hi/lo split (WO, into the stacked A12 arrays at row 1024)
__global__ void split_f16(const float* __restrict__ x,
                          __half* __restrict__ h, __half* __restrict__ l, int n4)
{
    int i = blockIdx.x * blockDim.x + threadIdx.x;
    if (i >= n4) return;
    float4 v = ((const float4*)x)[i];
    __half hh[4], ll[4];
    split1h(v.x, hh[0], ll[0]); split1h(v.y, hh[1], ll[1]);
    split1h(v.z, hh[2], ll[2]); split1h(v.w, hh[3], ll[3]);
    ((uint2*)h)[i] = *(uint2*)hh;
    ((uint2*)l)[i] = *(uint2*)ll;
}

// split + transpose (D,D) fp32 -> fp16 planes of W^T  (CLOCK CANARY kernel)
__global__ void split_tr(const float* __restrict__ W,
                         __half* __restrict__ Th, __half* __restrict__ Tl)
{
    __shared__ float t[32][33];
    const int c0 = blockIdx.x * 32;
    const int r0 = blockIdx.y * 32;
    const int tx = threadIdx.x, ty = threadIdx.y;
#pragma unroll
    for (int i = 0; i < 32; i += 8)
        t[ty + i][tx] = W[(long)(r0 + ty + i) * D_MODEL + c0 + tx];
    __syncthreads();
#pragma unroll
    for (int i = 0; i < 32; i += 8) {
        float v = t[tx][ty + i];
        __half h, l;
        split1h(v, h, l);
        const long o = (long)(c0 + ty + i) * D_MODEL + r0 + tx;
        Th[o] = h;  Tl[o] = l;
    }
}

// ---------------------------------------------------------------------------
// prep_vec: b2[0:1024]=bK@WQ, b2[1024:2048]=bK@WO^T, vb[0:1024]=WK^T bQ,
// vb[1024]=bQ.bK.  One block per output element.
// ---------------------------------------------------------------------------
__global__ void prep_vec(const __half* __restrict__ A12h,
                         const __half* __restrict__ A12l,
                         const float* __restrict__ WO,
                         const __half* __restrict__ WKTh,
                         const __half* __restrict__ WKTl,
                         const float* __restrict__ bK,
                         const float* __restrict__ bQ,
                         float* __restrict__ b2, float* __restrict__ vb)
{
    const int n = blockIdx.x;
    const int t = threadIdx.x;
    float s = 0.f;

    if (n < 1024) {
        const uint2 h2 = ((const uint2*)(A12h + (long)n * D_MODEL))[t];
        const uint2 l2 = ((const uint2*)(A12l + (long)n * D_MODEL))[t];
        const __half* hp = (const __half*)&h2;
        const __half* lp = (const __half*)&l2;
        float4 b = ((const float4*)bK)[t];
        s = (__half2float(hp[0]) + __half2float(lp[0])) * b.x
          + (__half2float(hp[1]) + __half2float(lp[1])) * b.y
          + (__half2float(hp[2]) + __half2float(lp[2])) * b.z
          + (__half2float(hp[3]) + __half2float(lp[3])) * b.w;
    } else if (n < 2048) {
        float4 w = ((const float4*)(WO + (long)(n - 1024) * D_MODEL))[t];
        float4 b = ((const float4*)bK)[t];
        s = w.x * b.x + w.y * b.y + w.z * b.z + w.w * b.w;
    } else if (n < 3072) {
        const uint2 h2 = ((const uint2*)(WKTh + (long)(n - 2048) * D_MODEL))[t];
        const uint2 l2 = ((const uint2*)(WKTl + (long)(n - 2048) * D_MODEL))[t];
        const __half* hp = (const __half*)&h2;
        const __half* lp = (const __half*)&l2;
        float4 b = ((const float4*)bQ)[t];
        s = (__half2float(hp[0]) + __half2float(lp[0])) * b.x
          + (__half2float(hp[1]) + __half2float(lp[1])) * b.y
          + (__half2float(hp[2]) + __half2float(lp[2])) * b.z
          + (__half2float(hp[3]) + __half2float(lp[3])) * b.w;
    } else {
        float4 q = ((const float4*)bQ)[t];
        float4 b = ((const float4*)bK)[t];
        s = q.x * b.x + q.y * b.y + q.z * b.z + q.w * b.w;
    }

    __shared__ float red[8];
#pragma unroll
    for (int o = 16; o; o >>= 1) s += __shfl_xor_sync(0xffffffffu, s, o);
    if ((t & 31) == 0) red[t >> 5] = s;
    __syncthreads();
    if (t == 0) {
        float tot = 0.f;
#pragma unroll
        for (int i = 0; i < 8; i++) tot += red[i];
        if (n < 2048)      b2[n] = tot;
        else if (n < 3072) vb[n - 2048] = tot;
        else               vb[1024] = tot;
    }
}

// ---------------------------------------------------------------------------
// gather (single fp16 plane) + score-bias
// ---------------------------------------------------------------------------
__global__ void gather_sb(const float* __restrict__ E,
                          const int* __restrict__ idx,
                          const float* __restrict__ vb,
                          __half* __restrict__ Gh,
                          float* __restrict__ sb)
{
    const int r = blockIdx.x;
    int s = idx[r];
    if (s < 0) s = 0;
    const int i = threadIdx.x;
    float4 v = ((const float4*)(E + (long)s * D_MODEL))[i];
    __half hh[4];
    hh[0] = __float2half_rn(v.x); hh[1] = __float2half_rn(v.y);
    hh[2] = __float2half_rn(v.z); hh[3] = __float2half_rn(v.w);
    ((uint2*)(Gh + (long)r * D_MODEL))[i] = *(uint2*)hh;

    float4 w = ((const float4*)vb)[i];
    float d = v.x * w.x + v.y * w.y + v.z * w.z + v.w * w.w;
    __shared__ float red[8];
#pragma unroll
    for (int o = 16; o; o >>= 1) d += __shfl_xor_sync(0xffffffffu, d, o);
    if ((i & 31) == 0) red[i >> 5] = d;
    __syncthreads();
    if (i == 0) {
        float tot = vb[1024];
#pragma unroll
        for (int k = 0; k < 8; k++) tot += red[k];
        sb[r] = tot;
    }
}

// ---------------------------------------------------------------------------
// per-batch fp16 transpose of the EO half of EQEO -> EOT[b] (D x NBE)
// ---------------------------------------------------------------------------
__global__ void transpose_f16(const __half* __restrict__ EQEO,
                              __half* __restrict__ EOT)
{
    __shared__ __half t[32][34];
    const int b  = blockIdx.z;
    const int c0 = blockIdx.x * 32;
    const int r0 = blockIdx.y * 32;
    const int tx = threadIdx.x, ty = threadIdx.y;
#pragma unroll
    for (int i = 0; i < 32; i += 8)
        t[ty + i][tx] = EQEO[(long)(b * NBE + r0 + ty + i) * 2048 + 1024 + c0 + tx];
    __syncthreads();
#pragma unroll
    for (int i = 0; i < 32; i += 8)
        EOT[(long)b * NBE * D_MODEL + (long)(c0 + ty + i) * NBE + r0 + tx]
            = t[tx][ty + i];
}

// ---------------------------------------------------------------------------
// Row LayerNorm over D=1024 (biased var, eps=1e-5).
// ---------------------------------------------------------------------------
__global__ void layernorm_k(const float* __restrict__ X,
                            const float* __restrict__ g,
                            const float* __restrict__ b,
                            float* __restrict__ O)
{
    const int row = blockIdx.x;
    const int t   = threadIdx.x;
    const float* x = X + (long)row * D_MODEL;

    float4 v = *(const float4*)(x + t * 4);
    float s  = v.x + v.y + v.z + v.w;
    float sq = v.x * v.x + v.y * v.y + v.z * v.z + v.w * v.w;

    __shared__ float rs[8], rq[8];
#pragma unroll
    for (int o = 16; o; o >>= 1) {
        s  += __shfl_xor_sync(0xffffffffu, s,  o);
        sq += __shfl_xor_sync(0xffffffffu, sq, o);
    }
    if ((t & 31) == 0) { rs[t >> 5] = s; rq[t >> 5] = sq; }
    __syncthreads();
    float S = 0.f, Q = 0.f;
#pragma unroll
    for (int i = 0; i < 8; i++) { S += rs[i]; Q += rq[i]; }

    float mu  = S * (1.f / 1024.f);
    float var = Q * (1.f / 1024.f) - mu * mu;
    float inv = rsqrtf(var + 1e-5f);

    float4 gg = *(const float4*)(g + t * 4);
    float4 bb = *(const float4*)(b + t * 4);
    float4 o;
    o.x = (v.x - mu) * inv * gg.x + bb.x;
    o.y = (v.y - mu) * inv * gg.y + bb.y;
    o.z = (v.z - mu) * inv * gg.z + bb.z;
    o.w = (v.w - mu) * inv * gg.w + bb.w;
    *(float4*)(O + (long)row * D_MODEL + t * 4) = o;
}

// ---------------------------------------------------------------------------
extern "C" void kernel_launch(void* const* d_in, const int* in_sizes, int n_in,
                              void* d_out, int out_size)
{
    const float* query   = (const float*)d_in[0];
    const float* ent_emb = (const float*)d_in[1];
    const int*   idx     = (const int*)  d_in[2];
    const float* WQ_w = (const float*)d_in[4];
    const float* WQ_b = (const float*)d_in[5];
    const float* WK_w = (const float*)d_in[6];
    const float* WK_b = (const float*)d_in[7];
    const float* WO_w = (const float*)d_in[8];
    const float* WO_b = (const float*)d_in[9];
    const float* ln_g = (const float*)d_in[10];
    const float* ln_b = (const float*)d_in[11];
    float* out = (float*)d_out;

    __half *qh, *A12h, *A12l, *WKTh, *WKTl, *Gh, *T12, *EQEO, *EOT, *Wh;
    float *sb, *vb, *b2, *P;
    cudaGetSymbolAddress((void**)&qh,   g_qh);
    cudaGetSymbolAddress((void**)&A12h, g_A12h); cudaGetSymbolAddress((void**)&A12l, g_A12l);
    cudaGetSymbolAddress((void**)&WKTh, g_WKTh); cudaGetSymbolAddress((void**)&WKTl, g_WKTl);
    cudaGetSymbolAddress((void**)&Gh,   g_Gh);
    cudaGetSymbolAddress((void**)&T12,  g_T12);
    cudaGetSymbolAddress((void**)&EQEO, g_EQEO);
    cudaGetSymbolAddress((void**)&EOT,  g_EOT);
    cudaGetSymbolAddress((void**)&Wh,   g_Wh);
    cudaGetSymbolAddress((void**)&sb,   g_sb);
    cudaGetSymbolAddress((void**)&vb,   g_vb);
    cudaGetSymbolAddress((void**)&b2,   g_b2);
    cudaGetSymbolAddress((void**)&P,    g_P);

    cudaFuncSetAttribute((const void*)gemm2<2, true >,
        cudaFuncAttributeMaxDynamicSharedMemorySize, GSMEM_A2);
    cudaFuncSetAttribute((const void*)gemm2<1, true >,
        cudaFuncAttributeMaxDynamicSharedMemorySize, GSMEM_A1);
    cudaFuncSetAttribute((const void*)gemm2<1, false>,
        cudaFuncAttributeMaxDynamicSharedMemorySize, GSMEM_A1);
    cudaFuncSetAttribute((const void*)sgemm_softmax,
        cudaFuncAttributeMaxDynamicSharedMemorySize, GSMEM_F);

    const int DD4 = D_MODEL * D_MODEL / 4;
    const long DD = (long)D_MODEL * D_MODEL;

    // 0. input preprocessing
    tohalf<<<(ML * D_MODEL / 4 + 255) / 256, 256>>>(query, qh, ML * D_MODEL / 4);
    split_tr<<<dim3(32, 32), dim3(32, 8)>>>(WQ_w, A12h, A12l);
    split_f16<<<(DD4 + 255) / 256, 256>>>(WO_w, A12h + DD, A12l + DD, DD4);
    split_tr<<<dim3(32, 32), dim3(32, 8)>>>(WK_w, WKTh, WKTl);
    prep_vec<<<3073, 256>>>(A12h, A12l, WO_w, WKTh, WKTl, WK_b, WQ_b, b2, vb);
    gather_sb<<<MB, 256>>>(ent_emb, idx, vb, Gh, sb);

    // 1. merged weight product: [T1;T2] = [WQ^T;WO] @ WK  (2-term A, one GEMM)
    gemm2<2, true><<<dim3(8, 16, 1), 256, GSMEM_A2>>>(
        A12h, A12l, 0, WKTh, 0, D_MODEL, nullptr, T12, 0,
        D_MODEL, D_MODEL, nullptr, 0);

    // 2. EQEO = G @ [T1;T2]^T + bias2   [4096 x 2048 x 1024], 1-term A
    gemm2<1, true><<<dim3(16, 32, 1), 256, GSMEM_A1>>>(
        Gh, nullptr, 0, T12, 0, D_MODEL, nullptr, EQEO, 0,
        2048, D_MODEL, b2, 0);

    // 3. fused scores + masked softmax -> fp16 weights
    sgemm_softmax<<<dim3(1, 16, BATCH), 256, GSMEM_F>>>(
        qh, EQEO, sb, idx, Wh);

    // 4. EOT[b] = EO[b]^T
    transpose_f16<<<dim3(32, 8, BATCH), dim3(32, 8)>>>(EQEO, EOT);

    // 5. P[b] = W[b] @ EOT[b]^T + bO   (1-term A)
    gemm2<1, false><<<dim3(8, 8, BATCH), 256, GSMEM_A1>>>(
        Wh, nullptr, (long)LQ * NBE, EOT, (long)D_MODEL * NBE, NBE,
        P, nullptr, (long)LQ * D_MODEL, D_MODEL, NBE, WO_b, 0);

    // 6. LayerNorm -> out
    layernorm_k<<<ML, 256>>>(P, ln_g, ln_b, out);
}